// round 1
// baseline (speedup 1.0000x reference)
#include <cuda_runtime.h>
#include <cuda_bf16.h>

#define NROWS 4096
#define DIM 256
#define DFF 512
#define NHEAD 8
#define DHEAD 64
#define NCHAIN 64
#define NBATCH 8
#define YW 1024   // 2*DFF

// ---------------- scratch (device globals; no allocation allowed) ----------------
__device__ float g_k[NROWS * DFF];
__device__ float g_v[NROWS * DFF];
__device__ float g_q[NROWS * DFF];
__device__ float g_bp[NROWS * YW];
__device__ float g_y[NROWS * YW];
__device__ float g_bmean[NBATCH * YW];
__device__ float g_mask[NROWS];
__device__ int   g_mask_mode; // 1 = byte-per-element, 0 = 4-byte-per-element

// ---------------- mask dtype detection ----------------
// bool stored as 1 byte -> ~90% of first N bytes nonzero.
// int32 (0/1) -> <=25% nonzero bytes; float32 (0/1.0f) -> <=45%.
__global__ void detect_mask_kernel(const unsigned char* __restrict__ m) {
    __shared__ int s[256];
    int t = threadIdx.x;
    int c = 0;
    for (int i = t; i < NROWS; i += 256) c += (m[i] != 0);
    s[t] = c;
    __syncthreads();
    for (int off = 128; off > 0; off >>= 1) {
        if (t < off) s[t] += s[t + off];
        __syncthreads();
    }
    if (t == 0) g_mask_mode = (2 * s[0] > NROWS) ? 1 : 0;
}

__global__ void expand_mask_kernel(const void* __restrict__ mp) {
    int i = blockIdx.x * 256 + threadIdx.x;
    if (i >= NROWS) return;
    bool on;
    if (g_mask_mode)
        on = ((const unsigned char*)mp)[i] != 0;
    else
        on = ((const unsigned int*)mp)[i] != 0u;  // works for int32 1 and float32 1.0f
    g_mask[i] = on ? 1.0f : 0.0f;
}

// ---------------- GELU (jax.nn.gelu, approximate=True / tanh) ----------------
__device__ __forceinline__ float gelu_tanh(float x) {
    float x3 = x * x * x;
    float inner = 0.7978845608028654f * (x + 0.044715f * x3);
    return 0.5f * x * (1.0f + tanhf(inner));
}

// ---------------- generic fp32 GEMM: C = act(X @ W + bias) ----------------
// X: [M=4096, K] row-major (row stride K)
// W: [K, Ncols] row-major
// optional: A-element += bmean[batch[row]][k]  (final-GEMM bias gather)
// BM=BN=64, BK=16, 256 threads, 4x4 micro-tile
__global__ void gemm_kernel(const float* __restrict__ X,
                            const float* __restrict__ W,
                            const float* __restrict__ bias,
                            float* __restrict__ C,
                            int K, int Ncols, int act,
                            const int* __restrict__ batch,
                            const float* __restrict__ bmean)
{
    __shared__ float As[16][68]; // [k][m], padded
    __shared__ float Ws[16][64]; // [k][n]

    int t  = threadIdx.x;
    int m0 = blockIdx.y * 64;
    int n0 = blockIdx.x * 64;
    int tx = t & 15, ty = t >> 4;

    int arow  = m0 + (t >> 2);
    int acol0 = (t & 3) * 4;
    int wrow  = t >> 4;
    int wcol  = n0 + (t & 15) * 4;

    int brow = (batch != nullptr) ? batch[arow] : 0;

    float acc[4][4];
#pragma unroll
    for (int i = 0; i < 4; i++)
#pragma unroll
        for (int j = 0; j < 4; j++) acc[i][j] = 0.f;

    for (int k0 = 0; k0 < K; k0 += 16) {
        float4 xa = *(const float4*)(X + (size_t)arow * K + k0 + acol0);
        if (bmean != nullptr) {
            float4 bm = *(const float4*)(bmean + (size_t)brow * K + k0 + acol0);
            xa.x += bm.x; xa.y += bm.y; xa.z += bm.z; xa.w += bm.w;
        }
        As[acol0 + 0][t >> 2] = xa.x;
        As[acol0 + 1][t >> 2] = xa.y;
        As[acol0 + 2][t >> 2] = xa.z;
        As[acol0 + 3][t >> 2] = xa.w;

        *(float4*)&Ws[wrow][(t & 15) * 4] =
            *(const float4*)(W + (size_t)(k0 + wrow) * Ncols + wcol);

        __syncthreads();

#pragma unroll
        for (int kk = 0; kk < 16; kk++) {
            float4 af = *(const float4*)&As[kk][ty * 4];
            float4 bf = *(const float4*)&Ws[kk][tx * 4];
            acc[0][0] += af.x * bf.x; acc[0][1] += af.x * bf.y;
            acc[0][2] += af.x * bf.z; acc[0][3] += af.x * bf.w;
            acc[1][0] += af.y * bf.x; acc[1][1] += af.y * bf.y;
            acc[1][2] += af.y * bf.z; acc[1][3] += af.y * bf.w;
            acc[2][0] += af.z * bf.x; acc[2][1] += af.z * bf.y;
            acc[2][2] += af.z * bf.z; acc[2][3] += af.z * bf.w;
            acc[3][0] += af.w * bf.x; acc[3][1] += af.w * bf.y;
            acc[3][2] += af.w * bf.z; acc[3][3] += af.w * bf.w;
        }
        __syncthreads();
    }

#pragma unroll
    for (int ii = 0; ii < 4; ii++) {
        int r = m0 + ty * 4 + ii;
        float4 o;
        float* po = &o.x;
#pragma unroll
        for (int jj = 0; jj < 4; jj++) {
            int cc = n0 + tx * 4 + jj;
            float v = acc[ii][jj];
            if (bias) v += bias[cc];
            if (act)  v = gelu_tanh(v);
            po[jj] = v;
        }
        *(float4*)(C + (size_t)r * Ncols + n0 + tx * 4) = o;
    }
}

// ---------------- per-batch masked mean of bias projection ----------------
// grid (NBATCH, 8), block 128: each block handles 128 columns of one batch
__global__ void bias_mean_kernel(const int* __restrict__ batch) {
    int b   = blockIdx.x;
    int col = blockIdx.y * 128 + threadIdx.x;
    float acc = 0.f, cnt = 0.f;
    for (int i = 0; i < NROWS; i++) {
        if (batch[i] == b) {
            float w = g_mask[i];
            cnt += w;
            acc += w * g_bp[(size_t)i * YW + col];
        }
    }
    g_bmean[b * YW + col] = acc / fmaxf(cnt, 1e-6f);
}

// ---------------- fused segment outer-product mean + attention apply ----------------
// One block per (segment c, head h).
//  pass1: build member list (bit31 = masked)
//  pass2: M = sum_{masked members} k_i v_i^T / count    (regs -> smem, 64x64)
//  pass3: for every member i: y[i, h*128 + col_off + a] = sum_b M[a][b] * q[i,h,b]
__global__ void seg_kernel(const float* __restrict__ kmat,
                           const float* __restrict__ vmat,
                           const float* __restrict__ qmat,
                           const int* __restrict__ seg,
                           float* __restrict__ y,
                           int col_off)
{
    int c = blockIdx.x;
    int h = blockIdx.y;
    int t = threadIdx.x;

    __shared__ int   list[NROWS];
    __shared__ int   cnt;
    __shared__ float A[64 * 65];
    __shared__ float kv[128];
    __shared__ float qv[4][64];
    __shared__ float red[256];

    if (t == 0) cnt = 0;
    __syncthreads();

    for (int i = t; i < NROWS; i += 256) {
        if (seg[i] == c) {
            int p = atomicAdd(&cnt, 1);
            list[p] = i | ((g_mask[i] > 0.5f) ? 0x80000000 : 0);
        }
    }
    __syncthreads();
    int n = cnt;

    // masked count
    float lc = 0.f;
    for (int m = t; m < n; m += 256) lc += (list[m] < 0) ? 1.f : 0.f;
    red[t] = lc;
    __syncthreads();
    for (int off = 128; off > 0; off >>= 1) {
        if (t < off) red[t] += red[t + off];
        __syncthreads();
    }
    float inv = 1.f / fmaxf(red[0], 1e-6f);

    // accumulate outer products
    float acc[16];
#pragma unroll
    for (int j = 0; j < 16; j++) acc[j] = 0.f;
    int a0 = t >> 2;
    int bb = (t & 3) * 16;

    for (int m = 0; m < n; m++) {
        int e = list[m];
        int i = e & 0x7FFFFFFF;
        if (t < 128) {
            kv[t] = (t < 64) ? kmat[(size_t)i * DFF + h * DHEAD + t]
                             : vmat[(size_t)i * DFF + h * DHEAD + (t - 64)];
        }
        __syncthreads();
        if (e < 0) {
            float ka = kv[a0];
#pragma unroll
            for (int j = 0; j < 16; j++) acc[j] += ka * kv[64 + bb + j];
        }
        __syncthreads();
    }
#pragma unroll
    for (int j = 0; j < 16; j++) A[a0 * 65 + bb + j] = acc[j] * inv;
    __syncthreads();

    // apply: 4 members at a time
    for (int base = 0; base < n; base += 4) {
        int sub = t >> 6;
        int a   = t & 63;
        int m   = base + sub;
        int idx = -1;
        if (m < n) {
            idx = list[m] & 0x7FFFFFFF;
            qv[sub][a] = qmat[(size_t)idx * DFF + h * DHEAD + a];
        }
        __syncthreads();
        if (m < n) {
            float s = 0.f;
#pragma unroll
            for (int b = 0; b < 64; b++) s += A[a * 65 + b] * qv[sub][b];
            y[(size_t)idx * YW + h * 128 + col_off + a] = s;
        }
        __syncthreads();
    }
}

// ---------------- launch ----------------
extern "C" void kernel_launch(void* const* d_in, const int* in_sizes, int n_in,
                              void* d_out, int out_size)
{
    const float* local   = (const float*)d_in[0];
    const int*   chain   = (const int*)  d_in[1];
    const int*   batch   = (const int*)  d_in[2];
    const void*  mask    = d_in[3];
    const float* W_key   = (const float*)d_in[4];
    const float* b_key   = (const float*)d_in[5];
    const float* W_value = (const float*)d_in[6];
    const float* b_value = (const float*)d_in[7];
    const float* W_query = (const float*)d_in[8];
    const float* b_query = (const float*)d_in[9];
    const float* W_bias  = (const float*)d_in[10];
    const float* b_bias  = (const float*)d_in[11];
    const float* W_out   = (const float*)d_in[12];
    float* out = (float*)d_out;

    float *gk, *gv, *gq, *gbp, *gy, *gbm;
    cudaGetSymbolAddress((void**)&gk,  g_k);
    cudaGetSymbolAddress((void**)&gv,  g_v);
    cudaGetSymbolAddress((void**)&gq,  g_q);
    cudaGetSymbolAddress((void**)&gbp, g_bp);
    cudaGetSymbolAddress((void**)&gy,  g_y);
    cudaGetSymbolAddress((void**)&gbm, g_bmean);

    detect_mask_kernel<<<1, 256>>>((const unsigned char*)mask);
    expand_mask_kernel<<<NROWS / 256, 256>>>(mask);

    // projections: k (gelu), v, q (gelu), bias proj
    gemm_kernel<<<dim3(DFF / 64, NROWS / 64), 256>>>(local, W_key,   b_key,   gk,  DIM, DFF, 1, nullptr, nullptr);
    gemm_kernel<<<dim3(DFF / 64, NROWS / 64), 256>>>(local, W_value, b_value, gv,  DIM, DFF, 0, nullptr, nullptr);
    gemm_kernel<<<dim3(DFF / 64, NROWS / 64), 256>>>(local, W_query, b_query, gq,  DIM, DFF, 1, nullptr, nullptr);
    gemm_kernel<<<dim3(YW  / 64, NROWS / 64), 256>>>(local, W_bias,  b_bias,  gbp, DIM, YW,  0, nullptr, nullptr);

    bias_mean_kernel<<<dim3(NBATCH, YW / 128), 128>>>(batch);

    // segment fused: chain -> first 64 cols per head, batch -> second 64
    seg_kernel<<<dim3(NCHAIN, NHEAD), 256>>>(gk, gv, gq, chain, gy, 0);
    seg_kernel<<<dim3(NBATCH, NHEAD), 256>>>(gk, gv, gq, batch, gy, DHEAD);

    // out = (y + bmean[batch]) @ W_out
    gemm_kernel<<<dim3(DIM / 64, NROWS / 64), 256>>>(gy, W_out, nullptr, out, YW, DIM, 0, batch, gbm);
}

// round 2
// speedup vs baseline: 1.9837x; 1.9837x over previous
#include <cuda_runtime.h>
#include <cuda_bf16.h>

#define NROWS 4096
#define DIM 256
#define DFF 512
#define NHEAD 8
#define DHEAD 64
#define NCHAIN 64
#define NBATCH 8
#define YW 1024   // 2*DFF
#define CH_STRIDE 256
#define BA_STRIDE 1024

// ---------------- scratch (device globals; no allocation allowed) ----------------
__device__ float g_k[NROWS * DFF];
__device__ float g_v[NROWS * DFF];
__device__ float g_q[NROWS * DFF];
__device__ float g_bp[NROWS * YW];
__device__ float g_y[NROWS * YW];
__device__ float g_bmean[NBATCH * YW];
__device__ float g_mask[NROWS];
__device__ int   g_mask_mode;

__device__ int   g_list_chain[NCHAIN * CH_STRIDE];
__device__ int   g_list_batch[NBATCH * BA_STRIDE];
__device__ int   g_cnt_chain[NCHAIN];
__device__ int   g_cnt_batch[NBATCH];
__device__ float g_minv_chain[NCHAIN];
__device__ float g_minv_batch[NBATCH];

// ---------------- mask dtype detection ----------------
__global__ void detect_mask_kernel(const unsigned char* __restrict__ m) {
    __shared__ int s[256];
    int t = threadIdx.x;
    int c = 0;
    for (int i = t; i < NROWS; i += 256) c += (m[i] != 0);
    s[t] = c;
    __syncthreads();
    for (int off = 128; off > 0; off >>= 1) {
        if (t < off) s[t] += s[t + off];
        __syncthreads();
    }
    if (t == 0) g_mask_mode = (2 * s[0] > NROWS) ? 1 : 0;
}

__global__ void expand_mask_kernel(const void* __restrict__ mp) {
    int i = blockIdx.x * 256 + threadIdx.x;
    if (i >= NROWS) return;
    bool on;
    if (g_mask_mode)
        on = ((const unsigned char*)mp)[i] != 0;
    else
        on = ((const unsigned int*)mp)[i] != 0u;
    g_mask[i] = on ? 1.0f : 0.0f;
}

// ---------------- deterministic ordered member-list build ----------------
// one block per segment; ballot-compaction preserves ascending row order
__global__ void build_list_kernel(const int* __restrict__ seg,
                                  int* __restrict__ list, int stride,
                                  int* __restrict__ cnts,
                                  float* __restrict__ minv)
{
    int s = blockIdx.x;
    int t = threadIdx.x;
    int w = t >> 5, lane = t & 31;
    __shared__ int warp_cnt[8];
    __shared__ int warp_off[8];
    __shared__ int base_s;
    __shared__ int red[256];
    if (t == 0) base_s = 0;
    int mcount = 0;
    __syncthreads();

    for (int chunk = 0; chunk < NROWS / 256; chunk++) {
        int i = chunk * 256 + t;
        bool pred = (seg[i] == s);
        bool mk = pred && (g_mask[i] > 0.5f);
        unsigned ball = __ballot_sync(0xffffffffu, pred);
        int wpre = __popc(ball & ((1u << lane) - 1u));
        if (lane == 0) warp_cnt[w] = __popc(ball);
        __syncthreads();
        if (t == 0) {
            int acc = base_s;
            for (int j = 0; j < 8; j++) { warp_off[j] = acc; acc += warp_cnt[j]; }
            base_s = acc;
        }
        __syncthreads();
        if (pred) list[s * stride + warp_off[w] + wpre] = i | (mk ? 0x80000000 : 0);
        mcount += mk ? 1 : 0;
        __syncthreads();
    }

    red[t] = mcount;
    __syncthreads();
    for (int off = 128; off > 0; off >>= 1) {
        if (t < off) red[t] += red[t + off];
        __syncthreads();
    }
    if (t == 0) {
        cnts[s] = base_s;
        minv[s] = 1.0f / fmaxf((float)red[0], 1e-6f);
    }
}

// ---------------- GELU (tanh approx) ----------------
__device__ __forceinline__ float gelu_tanh(float x) {
    float x3 = x * x * x;
    float inner = 0.7978845608028654f * (x + 0.044715f * x3);
    return 0.5f * x * (1.0f + tanhf(inner));
}

// ---------------- generic fp32 GEMM: C = act(X @ W + bias) ----------------
__global__ void gemm_kernel(const float* __restrict__ X,
                            const float* __restrict__ W,
                            const float* __restrict__ bias,
                            float* __restrict__ C,
                            int K, int Ncols, int act,
                            const int* __restrict__ batch,
                            const float* __restrict__ bmean)
{
    __shared__ float As[16][68];
    __shared__ float Ws[16][64];

    int t  = threadIdx.x;
    int m0 = blockIdx.y * 64;
    int n0 = blockIdx.x * 64;
    int tx = t & 15, ty = t >> 4;

    int arow  = m0 + (t >> 2);
    int acol0 = (t & 3) * 4;
    int wrow  = t >> 4;
    int wcol  = n0 + (t & 15) * 4;

    int brow = (batch != nullptr) ? batch[arow] : 0;

    float acc[4][4];
#pragma unroll
    for (int i = 0; i < 4; i++)
#pragma unroll
        for (int j = 0; j < 4; j++) acc[i][j] = 0.f;

    for (int k0 = 0; k0 < K; k0 += 16) {
        float4 xa = *(const float4*)(X + (size_t)arow * K + k0 + acol0);
        if (bmean != nullptr) {
            float4 bm = *(const float4*)(bmean + (size_t)brow * K + k0 + acol0);
            xa.x += bm.x; xa.y += bm.y; xa.z += bm.z; xa.w += bm.w;
        }
        As[acol0 + 0][t >> 2] = xa.x;
        As[acol0 + 1][t >> 2] = xa.y;
        As[acol0 + 2][t >> 2] = xa.z;
        As[acol0 + 3][t >> 2] = xa.w;

        *(float4*)&Ws[wrow][(t & 15) * 4] =
            *(const float4*)(W + (size_t)(k0 + wrow) * Ncols + wcol);

        __syncthreads();

#pragma unroll
        for (int kk = 0; kk < 16; kk++) {
            float4 af = *(const float4*)&As[kk][ty * 4];
            float4 bf = *(const float4*)&Ws[kk][tx * 4];
            acc[0][0] += af.x * bf.x; acc[0][1] += af.x * bf.y;
            acc[0][2] += af.x * bf.z; acc[0][3] += af.x * bf.w;
            acc[1][0] += af.y * bf.x; acc[1][1] += af.y * bf.y;
            acc[1][2] += af.y * bf.z; acc[1][3] += af.y * bf.w;
            acc[2][0] += af.z * bf.x; acc[2][1] += af.z * bf.y;
            acc[2][2] += af.z * bf.z; acc[2][3] += af.z * bf.w;
            acc[3][0] += af.w * bf.x; acc[3][1] += af.w * bf.y;
            acc[3][2] += af.w * bf.z; acc[3][3] += af.w * bf.w;
        }
        __syncthreads();
    }

#pragma unroll
    for (int ii = 0; ii < 4; ii++) {
        int r = m0 + ty * 4 + ii;
        float4 o;
        float* po = &o.x;
#pragma unroll
        for (int jj = 0; jj < 4; jj++) {
            int cc = n0 + tx * 4 + jj;
            float v = acc[ii][jj];
            if (bias) v += bias[cc];
            if (act)  v = gelu_tanh(v);
            po[jj] = v;
        }
        *(float4*)(C + (size_t)r * Ncols + n0 + tx * 4) = o;
    }
}

// ---------------- per-batch masked mean via member lists ----------------
// grid (NBATCH, YW/256), block 256
__global__ void bias_mean_kernel(const int* __restrict__ list,
                                 const int* __restrict__ cnts,
                                 const float* __restrict__ minv)
{
    int b   = blockIdx.x;
    int col = blockIdx.y * 256 + threadIdx.x;
    const int* L = list + b * BA_STRIDE;
    int n = cnts[b];
    float a0 = 0.f, a1 = 0.f, a2 = 0.f, a3 = 0.f;
    int m = 0;
    for (; m + 4 <= n; m += 4) {
        int e0 = L[m], e1 = L[m + 1], e2 = L[m + 2], e3 = L[m + 3];
        if (e0 < 0) a0 += g_bp[(size_t)(e0 & 0x7fffffff) * YW + col];
        if (e1 < 0) a1 += g_bp[(size_t)(e1 & 0x7fffffff) * YW + col];
        if (e2 < 0) a2 += g_bp[(size_t)(e2 & 0x7fffffff) * YW + col];
        if (e3 < 0) a3 += g_bp[(size_t)(e3 & 0x7fffffff) * YW + col];
    }
    for (; m < n; m++) {
        int e = L[m];
        if (e < 0) a0 += g_bp[(size_t)(e & 0x7fffffff) * YW + col];
    }
    g_bmean[b * YW + col] = (a0 + a1 + a2 + a3) * minv[b];
}

// ---------------- fused segment outer-product mean + attention apply (tiled) ----------------
// block = (segment c, head h), 256 threads.
// phase 1: chunks of 64 members, bulk smem load, register-tiled A += K^T V
// phase 2: A (scaled) to smem; chunks of 64 members, Y = Q A^T
__global__ void seg_kernel(const float* __restrict__ kmat,
                           const float* __restrict__ vmat,
                           const float* __restrict__ qmat,
                           const int* __restrict__ list,
                           const int* __restrict__ cnts,
                           const float* __restrict__ minv,
                           float* __restrict__ y,
                           int stride, int col_off)
{
    int c = blockIdx.x;
    int h = blockIdx.y;
    int t = threadIdx.x;
    const int* L = list + c * stride;
    int n = cnts[c];
    float inv = minv[c];

    __shared__ __align__(16) float sm1[64 * 68]; // ks, then A
    __shared__ __align__(16) float sm2[64 * 68]; // vs, then qs

    int ty = t >> 4, tx = t & 15;
    int mloc = t >> 2;       // member slot this thread loads (4 threads/member)
    int part = t & 3;        // quarter of the 64-float row

    float acc[4][4];
#pragma unroll
    for (int i = 0; i < 4; i++)
#pragma unroll
        for (int j = 0; j < 4; j++) acc[i][j] = 0.f;

    int nchunks = (n + 63) >> 6;

    // ---- phase 1: accumulate A = sum_m mask * k_m v_m^T ----
    for (int ch = 0; ch < nchunks; ch++) {
        int mrow = ch * 64 + mloc;
        float4 kq[4], vq[4];
        if (mrow < n) {
            int e = L[mrow];
            int i = e & 0x7fffffff;
            float mkf = (e < 0) ? 1.f : 0.f;
            const float4* kp = (const float4*)(kmat + (size_t)i * DFF + h * DHEAD + part * 16);
            const float4* vp = (const float4*)(vmat + (size_t)i * DFF + h * DHEAD + part * 16);
#pragma unroll
            for (int j = 0; j < 4; j++) {
                float4 kk = kp[j];
                kq[j] = make_float4(kk.x * mkf, kk.y * mkf, kk.z * mkf, kk.w * mkf);
                vq[j] = vp[j];
            }
        } else {
#pragma unroll
            for (int j = 0; j < 4; j++) {
                kq[j] = make_float4(0.f, 0.f, 0.f, 0.f);
                vq[j] = make_float4(0.f, 0.f, 0.f, 0.f);
            }
        }
#pragma unroll
        for (int j = 0; j < 4; j++) {
            *(float4*)(sm1 + mloc * 68 + part * 16 + j * 4) = kq[j];
            *(float4*)(sm2 + mloc * 68 + part * 16 + j * 4) = vq[j];
        }
        __syncthreads();

#pragma unroll 4
        for (int m = 0; m < 64; m++) {
            float4 af = *(const float4*)(sm1 + m * 68 + ty * 4);
            float4 bf = *(const float4*)(sm2 + m * 68 + tx * 4);
            acc[0][0] += af.x * bf.x; acc[0][1] += af.x * bf.y;
            acc[0][2] += af.x * bf.z; acc[0][3] += af.x * bf.w;
            acc[1][0] += af.y * bf.x; acc[1][1] += af.y * bf.y;
            acc[1][2] += af.y * bf.z; acc[1][3] += af.y * bf.w;
            acc[2][0] += af.z * bf.x; acc[2][1] += af.z * bf.y;
            acc[2][2] += af.z * bf.z; acc[2][3] += af.z * bf.w;
            acc[3][0] += af.w * bf.x; acc[3][1] += af.w * bf.y;
            acc[3][2] += af.w * bf.z; acc[3][3] += af.w * bf.w;
        }
        __syncthreads();
    }

    // ---- write scaled A into sm1: A[a][b] ----
#pragma unroll
    for (int i = 0; i < 4; i++)
#pragma unroll
        for (int j = 0; j < 4; j++)
            sm1[(ty * 4 + i) * 68 + tx * 4 + j] = acc[i][j] * inv;
    __syncthreads();

    // ---- phase 2: Y[m][a] = sum_b Q[m][b] * A[a][b] ----
    for (int ch = 0; ch < nchunks; ch++) {
        int mrow = ch * 64 + mloc;
        float4 qq[4];
        if (mrow < n) {
            int i = L[mrow] & 0x7fffffff;
            const float4* qp = (const float4*)(qmat + (size_t)i * DFF + h * DHEAD + part * 16);
#pragma unroll
            for (int j = 0; j < 4; j++) qq[j] = qp[j];
        } else {
#pragma unroll
            for (int j = 0; j < 4; j++) qq[j] = make_float4(0.f, 0.f, 0.f, 0.f);
        }
#pragma unroll
        for (int j = 0; j < 4; j++)
            *(float4*)(sm2 + mloc * 68 + part * 16 + j * 4) = qq[j];
        __syncthreads();

        // thread: members m0 = ty*4 .. +3 of this chunk, cols a0 = tx*4 .. +3
        float o[4][4];
#pragma unroll
        for (int i = 0; i < 4; i++)
#pragma unroll
            for (int j = 0; j < 4; j++) o[i][j] = 0.f;

#pragma unroll 8
        for (int b = 0; b < 64; b += 4) {
#pragma unroll
            for (int i = 0; i < 4; i++) {
                float4 qf = *(const float4*)(sm2 + (ty * 4 + i) * 68 + b);
#pragma unroll
                for (int j = 0; j < 4; j++) {
                    float4 af = *(const float4*)(sm1 + (tx * 4 + j) * 68 + b);
                    o[i][j] += qf.x * af.x + qf.y * af.y + qf.z * af.z + qf.w * af.w;
                }
            }
        }

#pragma unroll
        for (int i = 0; i < 4; i++) {
            int mm = ch * 64 + ty * 4 + i;
            if (mm < n) {
                int irow = L[mm] & 0x7fffffff;
                float4 ov = make_float4(o[i][0], o[i][1], o[i][2], o[i][3]);
                *(float4*)(y + (size_t)irow * YW + h * 128 + col_off + tx * 4) = ov;
            }
        }
        __syncthreads();
    }
}

// ---------------- launch ----------------
extern "C" void kernel_launch(void* const* d_in, const int* in_sizes, int n_in,
                              void* d_out, int out_size)
{
    const float* local   = (const float*)d_in[0];
    const int*   chain   = (const int*)  d_in[1];
    const int*   batch   = (const int*)  d_in[2];
    const void*  mask    = d_in[3];
    const float* W_key   = (const float*)d_in[4];
    const float* b_key   = (const float*)d_in[5];
    const float* W_value = (const float*)d_in[6];
    const float* b_value = (const float*)d_in[7];
    const float* W_query = (const float*)d_in[8];
    const float* b_query = (const float*)d_in[9];
    const float* W_bias  = (const float*)d_in[10];
    const float* b_bias  = (const float*)d_in[11];
    const float* W_out   = (const float*)d_in[12];
    float* out = (float*)d_out;

    float *gk, *gv, *gq, *gbp, *gbm;
    int *glc, *glb, *gcc, *gcb;
    float *gmc, *gmb, *gy;
    cudaGetSymbolAddress((void**)&gk,  g_k);
    cudaGetSymbolAddress((void**)&gv,  g_v);
    cudaGetSymbolAddress((void**)&gq,  g_q);
    cudaGetSymbolAddress((void**)&gbp, g_bp);
    cudaGetSymbolAddress((void**)&gy,  g_y);
    cudaGetSymbolAddress((void**)&gbm, g_bmean);
    cudaGetSymbolAddress((void**)&glc, g_list_chain);
    cudaGetSymbolAddress((void**)&glb, g_list_batch);
    cudaGetSymbolAddress((void**)&gcc, g_cnt_chain);
    cudaGetSymbolAddress((void**)&gcb, g_cnt_batch);
    cudaGetSymbolAddress((void**)&gmc, g_minv_chain);
    cudaGetSymbolAddress((void**)&gmb, g_minv_batch);

    detect_mask_kernel<<<1, 256>>>((const unsigned char*)mask);
    expand_mask_kernel<<<NROWS / 256, 256>>>(mask);

    build_list_kernel<<<NCHAIN, 256>>>(chain, glc, CH_STRIDE, gcc, gmc);
    build_list_kernel<<<NBATCH, 256>>>(batch, glb, BA_STRIDE, gcb, gmb);

    gemm_kernel<<<dim3(DFF / 64, NROWS / 64), 256>>>(local, W_key,   b_key,   gk,  DIM, DFF, 1, nullptr, nullptr);
    gemm_kernel<<<dim3(DFF / 64, NROWS / 64), 256>>>(local, W_value, b_value, gv,  DIM, DFF, 0, nullptr, nullptr);
    gemm_kernel<<<dim3(DFF / 64, NROWS / 64), 256>>>(local, W_query, b_query, gq,  DIM, DFF, 1, nullptr, nullptr);
    gemm_kernel<<<dim3(YW  / 64, NROWS / 64), 256>>>(local, W_bias,  b_bias,  gbp, DIM, YW,  0, nullptr, nullptr);

    bias_mean_kernel<<<dim3(NBATCH, YW / 256), 256>>>(glb, gcb, gmb);

    seg_kernel<<<dim3(NCHAIN, NHEAD), 256>>>(gk, gv, gq, glc, gcc, gmc, gy, CH_STRIDE, 0);
    seg_kernel<<<dim3(NBATCH, NHEAD), 256>>>(gk, gv, gq, glb, gcb, gmb, gy, BA_STRIDE, DHEAD);

    gemm_kernel<<<dim3(DIM / 64, NROWS / 64), 256>>>(gy, W_out, nullptr, out, YW, DIM, 0, batch, gbm);
}

// round 3
// speedup vs baseline: 2.3569x; 1.1882x over previous
#include <cuda_runtime.h>
#include <cuda_bf16.h>

#define NROWS 4096
#define DIM 256
#define DFF 512
#define NHEAD 8
#define DHEAD 64
#define NCHAIN 64
#define NBATCH 8
#define YW 1024   // 2*DFF
#define CH_STRIDE 256
#define BA_STRIDE 1024
#define KSPLIT 8

// ---------------- scratch (device globals; no allocation allowed) ----------------
__device__ float g_k[NROWS * DFF];
__device__ float g_v[NROWS * DFF];
__device__ float g_q[NROWS * DFF];
__device__ float g_y[NROWS * YW];
__device__ float g_part[KSPLIT * NROWS * DIM];
__device__ float g_xsum[NBATCH * DIM];
__device__ float g_bmean[NBATCH * YW];
__device__ float g_mask[NROWS];
__device__ int   g_mask_mode;

__device__ int   g_list_chain[NCHAIN * CH_STRIDE];
__device__ int   g_list_batch[NBATCH * BA_STRIDE];
__device__ int   g_cnt_chain[NCHAIN];
__device__ int   g_cnt_batch[NBATCH];
__device__ float g_minv_chain[NCHAIN];
__device__ float g_minv_batch[NBATCH];

// ---------------- mask dtype detection ----------------
__global__ void detect_mask_kernel(const unsigned char* __restrict__ m) {
    __shared__ int s[256];
    int t = threadIdx.x;
    int c = 0;
    for (int i = t; i < NROWS; i += 256) c += (m[i] != 0);
    s[t] = c;
    __syncthreads();
    for (int off = 128; off > 0; off >>= 1) {
        if (t < off) s[t] += s[t + off];
        __syncthreads();
    }
    if (t == 0) g_mask_mode = (2 * s[0] > NROWS) ? 1 : 0;
}

__global__ void expand_mask_kernel(const void* __restrict__ mp) {
    int i = blockIdx.x * 256 + threadIdx.x;
    if (i >= NROWS) return;
    bool on;
    if (g_mask_mode)
        on = ((const unsigned char*)mp)[i] != 0;
    else
        on = ((const unsigned int*)mp)[i] != 0u;
    g_mask[i] = on ? 1.0f : 0.0f;
}

// ---------------- deterministic ordered member-list build (1024 threads) ----------------
__global__ void build_list_kernel(const int* __restrict__ seg,
                                  int* __restrict__ list, int stride,
                                  int* __restrict__ cnts,
                                  float* __restrict__ minv)
{
    int s = blockIdx.x;
    int t = threadIdx.x;
    int w = t >> 5, lane = t & 31;
    __shared__ int woff[32];
    __shared__ int wred[32];
    __shared__ int sbase, snext;
    if (t == 0) sbase = 0;
    int mcount = 0;
    __syncthreads();

    for (int c = 0; c < NROWS / 1024; c++) {
        int i = c * 1024 + t;
        bool pred = (seg[i] == s);
        bool mk = pred && (g_mask[i] > 0.5f);
        unsigned ball = __ballot_sync(0xffffffffu, pred);
        int wpre = __popc(ball & ((1u << lane) - 1u));
        if (lane == 0) woff[w] = __popc(ball);
        __syncthreads();
        if (w == 0) {
            int v = woff[lane];
            int sc = v;
            for (int o = 1; o < 32; o <<= 1) {
                int nb = __shfl_up_sync(0xffffffffu, sc, o);
                if (lane >= o) sc += nb;
            }
            woff[lane] = sbase + sc - v;
            if (lane == 31) snext = sbase + sc;
        }
        __syncthreads();
        if (pred) list[s * stride + woff[w] + wpre] = i | (mk ? 0x80000000 : 0);
        mcount += mk ? 1 : 0;
        if (t == 0) sbase = snext;
        __syncthreads();
    }

    for (int o = 16; o > 0; o >>= 1) mcount += __shfl_down_sync(0xffffffffu, mcount, o);
    if (lane == 0) wred[w] = mcount;
    __syncthreads();
    if (w == 0) {
        int v = wred[lane];
        for (int o = 16; o > 0; o >>= 1) v += __shfl_down_sync(0xffffffffu, v, o);
        if (lane == 0) {
            cnts[s] = sbase;
            minv[s] = 1.0f / fmaxf((float)v, 1e-6f);
        }
    }
}

// ---------------- GELU (tanh approx) ----------------
__device__ __forceinline__ float gelu_tanh(float x) {
    float x3 = x * x * x;
    float inner = 0.7978845608028654f * (x + 0.044715f * x3);
    return 0.5f * x * (1.0f + tanhf(inner));
}

// ---------------- fused k|v|q projection GEMM ----------------
// X [4096,256] @ {W} [256,512] -> g_k (gelu), g_v, g_q (gelu)
// BM=BN=128, BK=8, TM=TN=8, 256 threads, double-buffered
__global__ void __launch_bounds__(256) proj_gemm_kernel(
    const float* __restrict__ X,
    const float* __restrict__ Wk, const float* __restrict__ bk,
    const float* __restrict__ Wv, const float* __restrict__ bv,
    const float* __restrict__ Wq, const float* __restrict__ bq)
{
    __shared__ __align__(16) float As[2][8][132];
    __shared__ __align__(16) float Bs[2][8][128];

    int t  = threadIdx.x;
    int m0 = blockIdx.y * 128;
    int n0 = blockIdx.x * 128;            // 0..1536
    int sec = n0 >> 9;
    int wc  = n0 & 511;

    const float* W; const float* bias; float* C; int act;
    if (sec == 0)      { W = Wk; bias = bk; C = g_k; act = 1; }
    else if (sec == 1) { W = Wv; bias = bv; C = g_v; act = 0; }
    else               { W = Wq; bias = bq; C = g_q; act = 1; }

    int tx = t & 15, ty = t >> 4;
    int arow = t >> 1, acol = (t & 1) * 4;
    int brow = t >> 5, bcol = (t & 31) * 4;

    const float* Aptr = X + (size_t)(m0 + arow) * DIM + acol;
    const float* Bptr = W + (size_t)brow * DFF + wc + bcol;

    float acc[8][8];
#pragma unroll
    for (int i = 0; i < 8; i++)
#pragma unroll
        for (int j = 0; j < 8; j++) acc[i][j] = 0.f;

    float4 aR = *(const float4*)Aptr;
    float4 bR = *(const float4*)Bptr;

    As[0][acol + 0][arow] = aR.x;
    As[0][acol + 1][arow] = aR.y;
    As[0][acol + 2][arow] = aR.z;
    As[0][acol + 3][arow] = aR.w;
    *(float4*)&Bs[0][brow][bcol] = bR;
    __syncthreads();

    const int NK = DIM / 8;   // 32
    for (int kt = 0; kt < NK; kt++) {
        int cur = kt & 1;
        if (kt + 1 < NK) {
            aR = *(const float4*)(Aptr + (kt + 1) * 8);
            bR = *(const float4*)(Bptr + (size_t)(kt + 1) * 8 * DFF);
        }
#pragma unroll
        for (int kk = 0; kk < 8; kk++) {
            float4 a0 = *(const float4*)&As[cur][kk][ty * 8];
            float4 a1 = *(const float4*)&As[cur][kk][ty * 8 + 4];
            float4 b0 = *(const float4*)&Bs[cur][kk][tx * 8];
            float4 b1 = *(const float4*)&Bs[cur][kk][tx * 8 + 4];
            float av[8] = {a0.x, a0.y, a0.z, a0.w, a1.x, a1.y, a1.z, a1.w};
            float bw[8] = {b0.x, b0.y, b0.z, b0.w, b1.x, b1.y, b1.z, b1.w};
#pragma unroll
            for (int i = 0; i < 8; i++)
#pragma unroll
                for (int j = 0; j < 8; j++) acc[i][j] += av[i] * bw[j];
        }
        if (kt + 1 < NK) {
            int nxt = cur ^ 1;
            As[nxt][acol + 0][arow] = aR.x;
            As[nxt][acol + 1][arow] = aR.y;
            As[nxt][acol + 2][arow] = aR.z;
            As[nxt][acol + 3][arow] = aR.w;
            *(float4*)&Bs[nxt][brow][bcol] = bR;
            __syncthreads();
        }
    }

    float bb[8];
#pragma unroll
    for (int j = 0; j < 8; j++) bb[j] = bias[wc + tx * 8 + j];

#pragma unroll
    for (int i = 0; i < 8; i++) {
        int r = m0 + ty * 8 + i;
        float o[8];
#pragma unroll
        for (int j = 0; j < 8; j++) {
            float v = acc[i][j] + bb[j];
            o[j] = act ? gelu_tanh(v) : v;
        }
        float* cp = C + (size_t)r * DFF + wc + tx * 8;
        *(float4*)(cp)     = make_float4(o[0], o[1], o[2], o[3]);
        *(float4*)(cp + 4) = make_float4(o[4], o[5], o[6], o[7]);
    }
}

// ---------------- final GEMM, split-K: part[kz] = (y + bmean[batch])[:,kz] @ W_out[kz,:] ----------------
__global__ void __launch_bounds__(256) out_gemm_kernel(
    const float* __restrict__ Wout, const int* __restrict__ batch)
{
    __shared__ __align__(16) float As[2][8][132];
    __shared__ __align__(16) float Bs[2][8][128];

    int t  = threadIdx.x;
    int m0 = blockIdx.y * 128;
    int n0 = blockIdx.x * 128;     // 0 or 128
    int kz = blockIdx.z;
    int kbase = kz * (YW / KSPLIT);   // 128 per split

    int tx = t & 15, ty = t >> 4;
    int arow = t >> 1, acol = (t & 1) * 4;
    int brow = t >> 5, bcol = (t & 31) * 4;

    int row = m0 + arow;
    int bt  = batch[row];
    const float* Ay = g_y + (size_t)row * YW + kbase + acol;
    const float* Ab = g_bmean + (size_t)bt * YW + kbase + acol;
    const float* Bptr = Wout + (size_t)(kbase + brow) * DIM + n0 + bcol;

    float acc[8][8];
#pragma unroll
    for (int i = 0; i < 8; i++)
#pragma unroll
        for (int j = 0; j < 8; j++) acc[i][j] = 0.f;

    float4 ya = *(const float4*)Ay;
    float4 ba = *(const float4*)Ab;
    float4 aR = make_float4(ya.x + ba.x, ya.y + ba.y, ya.z + ba.z, ya.w + ba.w);
    float4 bR = *(const float4*)Bptr;

    As[0][acol + 0][arow] = aR.x;
    As[0][acol + 1][arow] = aR.y;
    As[0][acol + 2][arow] = aR.z;
    As[0][acol + 3][arow] = aR.w;
    *(float4*)&Bs[0][brow][bcol] = bR;
    __syncthreads();

    const int NK = (YW / KSPLIT) / 8;  // 16
    for (int kt = 0; kt < NK; kt++) {
        int cur = kt & 1;
        if (kt + 1 < NK) {
            float4 y2 = *(const float4*)(Ay + (kt + 1) * 8);
            float4 b2 = *(const float4*)(Ab + (kt + 1) * 8);
            aR = make_float4(y2.x + b2.x, y2.y + b2.y, y2.z + b2.z, y2.w + b2.w);
            bR = *(const float4*)(Bptr + (size_t)(kt + 1) * 8 * DIM);
        }
#pragma unroll
        for (int kk = 0; kk < 8; kk++) {
            float4 a0 = *(const float4*)&As[cur][kk][ty * 8];
            float4 a1 = *(const float4*)&As[cur][kk][ty * 8 + 4];
            float4 b0 = *(const float4*)&Bs[cur][kk][tx * 8];
            float4 b1 = *(const float4*)&Bs[cur][kk][tx * 8 + 4];
            float av[8] = {a0.x, a0.y, a0.z, a0.w, a1.x, a1.y, a1.z, a1.w};
            float bw[8] = {b0.x, b0.y, b0.z, b0.w, b1.x, b1.y, b1.z, b1.w};
#pragma unroll
            for (int i = 0; i < 8; i++)
#pragma unroll
                for (int j = 0; j < 8; j++) acc[i][j] += av[i] * bw[j];
        }
        if (kt + 1 < NK) {
            int nxt = cur ^ 1;
            As[nxt][acol + 0][arow] = aR.x;
            As[nxt][acol + 1][arow] = aR.y;
            As[nxt][acol + 2][arow] = aR.z;
            As[nxt][acol + 3][arow] = aR.w;
            *(float4*)&Bs[nxt][brow][bcol] = bR;
            __syncthreads();
        }
    }

#pragma unroll
    for (int i = 0; i < 8; i++) {
        int r = m0 + ty * 8 + i;
        float* pp = g_part + ((size_t)kz * NROWS + r) * DIM + n0 + tx * 8;
        *(float4*)(pp)     = make_float4(acc[i][0], acc[i][1], acc[i][2], acc[i][3]);
        *(float4*)(pp + 4) = make_float4(acc[i][4], acc[i][5], acc[i][6], acc[i][7]);
    }
}

__global__ void reduce_out_kernel(float* __restrict__ out) {
    int idx = (blockIdx.x * 256 + threadIdx.x) * 4;
    float4 s = make_float4(0.f, 0.f, 0.f, 0.f);
#pragma unroll
    for (int kz = 0; kz < KSPLIT; kz++) {
        float4 p = *(const float4*)(g_part + (size_t)kz * NROWS * DIM + idx);
        s.x += p.x; s.y += p.y; s.z += p.z; s.w += p.w;
    }
    *(float4*)(out + idx) = s;
}

// ---------------- per-batch masked sum of local rows ----------------
__global__ void batch_xsum_kernel(const float* __restrict__ local,
                                  const int* __restrict__ list,
                                  const int* __restrict__ cnts)
{
    int b   = blockIdx.x;
    int col = blockIdx.y * 128 + threadIdx.x;
    const int* L = list + b * BA_STRIDE;
    int n = cnts[b];
    float a0 = 0.f, a1 = 0.f, a2 = 0.f, a3 = 0.f;
    int m = 0;
    for (; m + 4 <= n; m += 4) {
        int e0 = L[m], e1 = L[m + 1], e2 = L[m + 2], e3 = L[m + 3];
        if (e0 < 0) a0 += local[(size_t)(e0 & 0x7fffffff) * DIM + col];
        if (e1 < 0) a1 += local[(size_t)(e1 & 0x7fffffff) * DIM + col];
        if (e2 < 0) a2 += local[(size_t)(e2 & 0x7fffffff) * DIM + col];
        if (e3 < 0) a3 += local[(size_t)(e3 & 0x7fffffff) * DIM + col];
    }
    for (; m < n; m++) {
        int e = L[m];
        if (e < 0) a0 += local[(size_t)(e & 0x7fffffff) * DIM + col];
    }
    g_xsum[b * DIM + col] = a0 + a1 + a2 + a3;
}

// ---------------- bmean = (xsum/cnt) @ W_bias + b_bias ----------------
__global__ void bmean_kernel(const float* __restrict__ W_bias,
                             const float* __restrict__ b_bias,
                             const float* __restrict__ minv)
{
    __shared__ float xs[DIM];
    int b = blockIdx.x;
    int j = blockIdx.y * 128 + threadIdx.x;
    for (int k = threadIdx.x; k < DIM; k += 128) xs[k] = g_xsum[b * DIM + k];
    __syncthreads();
    float inv = minv[b];
    float acc = 0.f;
#pragma unroll 8
    for (int k = 0; k < DIM; k++) acc += xs[k] * W_bias[(size_t)k * YW + j];
    g_bmean[b * YW + j] = acc * inv + b_bias[j];
}

// ---------------- fused segment outer-product mean + attention apply (tiled) ----------------
__global__ void seg_kernel(const float* __restrict__ kmat,
                           const float* __restrict__ vmat,
                           const float* __restrict__ qmat,
                           const int* __restrict__ list,
                           const int* __restrict__ cnts,
                           const float* __restrict__ minv,
                           float* __restrict__ y,
                           int stride, int col_off)
{
    int c = blockIdx.x;
    int h = blockIdx.y;
    int t = threadIdx.x;
    const int* L = list + c * stride;
    int n = cnts[c];
    float inv = minv[c];

    __shared__ __align__(16) float sm1[64 * 68];
    __shared__ __align__(16) float sm2[64 * 68];

    int ty = t >> 4, tx = t & 15;
    int mloc = t >> 2;
    int part = t & 3;

    float acc[4][4];
#pragma unroll
    for (int i = 0; i < 4; i++)
#pragma unroll
        for (int j = 0; j < 4; j++) acc[i][j] = 0.f;

    int nchunks = (n + 63) >> 6;

    for (int ch = 0; ch < nchunks; ch++) {
        int mrow = ch * 64 + mloc;
        float4 kq[4], vq[4];
        if (mrow < n) {
            int e = L[mrow];
            int i = e & 0x7fffffff;
            float mkf = (e < 0) ? 1.f : 0.f;
            const float4* kp = (const float4*)(kmat + (size_t)i * DFF + h * DHEAD + part * 16);
            const float4* vp = (const float4*)(vmat + (size_t)i * DFF + h * DHEAD + part * 16);
#pragma unroll
            for (int j = 0; j < 4; j++) {
                float4 kk = kp[j];
                kq[j] = make_float4(kk.x * mkf, kk.y * mkf, kk.z * mkf, kk.w * mkf);
                vq[j] = vp[j];
            }
        } else {
#pragma unroll
            for (int j = 0; j < 4; j++) {
                kq[j] = make_float4(0.f, 0.f, 0.f, 0.f);
                vq[j] = make_float4(0.f, 0.f, 0.f, 0.f);
            }
        }
#pragma unroll
        for (int j = 0; j < 4; j++) {
            *(float4*)(sm1 + mloc * 68 + part * 16 + j * 4) = kq[j];
            *(float4*)(sm2 + mloc * 68 + part * 16 + j * 4) = vq[j];
        }
        __syncthreads();

#pragma unroll 4
        for (int m = 0; m < 64; m++) {
            float4 af = *(const float4*)(sm1 + m * 68 + ty * 4);
            float4 bf = *(const float4*)(sm2 + m * 68 + tx * 4);
            acc[0][0] += af.x * bf.x; acc[0][1] += af.x * bf.y;
            acc[0][2] += af.x * bf.z; acc[0][3] += af.x * bf.w;
            acc[1][0] += af.y * bf.x; acc[1][1] += af.y * bf.y;
            acc[1][2] += af.y * bf.z; acc[1][3] += af.y * bf.w;
            acc[2][0] += af.z * bf.x; acc[2][1] += af.z * bf.y;
            acc[2][2] += af.z * bf.z; acc[2][3] += af.z * bf.w;
            acc[3][0] += af.w * bf.x; acc[3][1] += af.w * bf.y;
            acc[3][2] += af.w * bf.z; acc[3][3] += af.w * bf.w;
        }
        __syncthreads();
    }

#pragma unroll
    for (int i = 0; i < 4; i++)
#pragma unroll
        for (int j = 0; j < 4; j++)
            sm1[(ty * 4 + i) * 68 + tx * 4 + j] = acc[i][j] * inv;
    __syncthreads();

    for (int ch = 0; ch < nchunks; ch++) {
        int mrow = ch * 64 + mloc;
        float4 qq[4];
        if (mrow < n) {
            int i = L[mrow] & 0x7fffffff;
            const float4* qp = (const float4*)(qmat + (size_t)i * DFF + h * DHEAD + part * 16);
#pragma unroll
            for (int j = 0; j < 4; j++) qq[j] = qp[j];
        } else {
#pragma unroll
            for (int j = 0; j < 4; j++) qq[j] = make_float4(0.f, 0.f, 0.f, 0.f);
        }
#pragma unroll
        for (int j = 0; j < 4; j++)
            *(float4*)(sm2 + mloc * 68 + part * 16 + j * 4) = qq[j];
        __syncthreads();

        float o[4][4];
#pragma unroll
        for (int i = 0; i < 4; i++)
#pragma unroll
            for (int j = 0; j < 4; j++) o[i][j] = 0.f;

#pragma unroll 8
        for (int b = 0; b < 64; b += 4) {
#pragma unroll
            for (int i = 0; i < 4; i++) {
                float4 qf = *(const float4*)(sm2 + (ty * 4 + i) * 68 + b);
#pragma unroll
                for (int j = 0; j < 4; j++) {
                    float4 af = *(const float4*)(sm1 + (tx * 4 + j) * 68 + b);
                    o[i][j] += qf.x * af.x + qf.y * af.y + qf.z * af.z + qf.w * af.w;
                }
            }
        }

#pragma unroll
        for (int i = 0; i < 4; i++) {
            int mm = ch * 64 + ty * 4 + i;
            if (mm < n) {
                int irow = L[mm] & 0x7fffffff;
                float4 ov = make_float4(o[i][0], o[i][1], o[i][2], o[i][3]);
                *(float4*)(y + (size_t)irow * YW + h * 128 + col_off + tx * 4) = ov;
            }
        }
        __syncthreads();
    }
}

// ---------------- launch ----------------
extern "C" void kernel_launch(void* const* d_in, const int* in_sizes, int n_in,
                              void* d_out, int out_size)
{
    const float* local   = (const float*)d_in[0];
    const int*   chain   = (const int*)  d_in[1];
    const int*   batch   = (const int*)  d_in[2];
    const void*  mask    = d_in[3];
    const float* W_key   = (const float*)d_in[4];
    const float* b_key   = (const float*)d_in[5];
    const float* W_value = (const float*)d_in[6];
    const float* b_value = (const float*)d_in[7];
    const float* W_query = (const float*)d_in[8];
    const float* b_query = (const float*)d_in[9];
    const float* W_bias  = (const float*)d_in[10];
    const float* b_bias  = (const float*)d_in[11];
    const float* W_out   = (const float*)d_in[12];
    float* out = (float*)d_out;

    float *gk, *gv, *gq, *gy;
    int *glc, *glb, *gcc, *gcb;
    float *gmc, *gmb;
    cudaGetSymbolAddress((void**)&gk,  g_k);
    cudaGetSymbolAddress((void**)&gv,  g_v);
    cudaGetSymbolAddress((void**)&gq,  g_q);
    cudaGetSymbolAddress((void**)&gy,  g_y);
    cudaGetSymbolAddress((void**)&glc, g_list_chain);
    cudaGetSymbolAddress((void**)&glb, g_list_batch);
    cudaGetSymbolAddress((void**)&gcc, g_cnt_chain);
    cudaGetSymbolAddress((void**)&gcb, g_cnt_batch);
    cudaGetSymbolAddress((void**)&gmc, g_minv_chain);
    cudaGetSymbolAddress((void**)&gmb, g_minv_batch);

    detect_mask_kernel<<<1, 256>>>((const unsigned char*)mask);
    expand_mask_kernel<<<NROWS / 256, 256>>>(mask);

    build_list_kernel<<<NCHAIN, 1024>>>(chain, glc, CH_STRIDE, gcc, gmc);
    build_list_kernel<<<NBATCH, 1024>>>(batch, glb, BA_STRIDE, gcb, gmb);

    proj_gemm_kernel<<<dim3(1536 / 128, NROWS / 128), 256>>>(
        local, W_key, b_key, W_value, b_value, W_query, b_query);

    batch_xsum_kernel<<<dim3(NBATCH, DIM / 128), 128>>>(local, glb, gcb);
    bmean_kernel<<<dim3(NBATCH, YW / 128), 128>>>(W_bias, b_bias, gmb);

    seg_kernel<<<dim3(NCHAIN, NHEAD), 256>>>(gk, gv, gq, glc, gcc, gmc, gy, CH_STRIDE, 0);
    seg_kernel<<<dim3(NBATCH, NHEAD), 256>>>(gk, gv, gq, glb, gcb, gmb, gy, BA_STRIDE, DHEAD);

    out_gemm_kernel<<<dim3(DIM / 128, NROWS / 128, KSPLIT), 256>>>(W_out, batch);
    reduce_out_kernel<<<NROWS * DIM / 1024, 256>>>(out);
}

// round 5
// speedup vs baseline: 2.8178x; 1.1955x over previous
#include <cuda_runtime.h>
#include <cuda_bf16.h>
#include <cstdint>

#define NROWS 4096
#define DIM 256
#define DFF 512
#define NHEAD 8
#define DHEAD 64
#define NCHAIN 64
#define NBATCH 8
#define YW 1024
#define CH_STRIDE 256
#define BA_STRIDE 1024

// ================= mma.sync helpers (portable sm_80+ path) =================
__device__ __forceinline__ uint32_t smem_u32(const void* p) {
    uint32_t a;
    asm("{ .reg .u64 t; cvta.to.shared.u64 t, %1; cvt.u32.u64 %0, t; }" : "=r"(a) : "l"(p));
    return a;
}
__device__ __forceinline__ void mma_bf16(float* c, const uint32_t* a, const uint32_t* b) {
    asm volatile(
        "mma.sync.aligned.m16n8k16.row.col.f32.bf16.bf16.f32 "
        "{%0,%1,%2,%3}, {%4,%5,%6,%7}, {%8,%9}, {%0,%1,%2,%3};"
        : "+f"(c[0]), "+f"(c[1]), "+f"(c[2]), "+f"(c[3])
        : "r"(a[0]), "r"(a[1]), "r"(a[2]), "r"(a[3]), "r"(b[0]), "r"(b[1]));
}
__device__ __forceinline__ void ldsm_x4(uint32_t* r, uint32_t addr) {
    asm volatile("ldmatrix.sync.aligned.m8n8.x4.shared.b16 {%0,%1,%2,%3}, [%4];"
                 : "=r"(r[0]), "=r"(r[1]), "=r"(r[2]), "=r"(r[3]) : "r"(addr));
}
__device__ __forceinline__ void ldsm_x2(uint32_t* r, uint32_t addr) {
    asm volatile("ldmatrix.sync.aligned.m8n8.x2.shared.b16 {%0,%1}, [%2];"
                 : "=r"(r[0]), "=r"(r[1]) : "r"(addr));
}

#define SMS 40   // smem row stride in bf16 (80B rows: 16B-aligned, conflict-free ldmatrix)

// ================= scratch =================
__device__ float g_k[NROWS * DFF];
__device__ float g_v[NROWS * DFF];
__device__ float g_q[NROWS * DFF];
__device__ float g_y[NROWS * YW];
__device__ float g_xsum[NBATCH * DIM];
__device__ float g_bmean[NBATCH * YW];
__device__ float g_mask[NROWS];

__device__ __nv_bfloat16 g_lhi[NROWS * DIM];
__device__ __nv_bfloat16 g_llo[NROWS * DIM];
__device__ __nv_bfloat16 g_wthi[3 * DFF * DIM];   // [1536][256] = W^T for k|v|q
__device__ __nv_bfloat16 g_wtlo[3 * DFF * DIM];
__device__ __nv_bfloat16 g_yhi[NROWS * YW];
__device__ __nv_bfloat16 g_ylo[NROWS * YW];
__device__ __nv_bfloat16 g_wohi[DIM * YW];        // [256][1024] = W_out^T
__device__ __nv_bfloat16 g_wolo[DIM * YW];

__device__ int   g_list_chain[NCHAIN * CH_STRIDE];
__device__ int   g_list_batch[NBATCH * BA_STRIDE];
__device__ int   g_cnt_chain[NCHAIN];
__device__ int   g_cnt_batch[NBATCH];
__device__ float g_minv_chain[NCHAIN];
__device__ float g_minv_batch[NBATCH];

// ================= mask detect + expand =================
__global__ void mask_kernel(const unsigned char* __restrict__ m) {
    __shared__ int s[1024];
    __shared__ int mode;
    int t = threadIdx.x;
    int c = 0;
    for (int i = t; i < NROWS; i += 1024) c += (m[i] != 0);
    s[t] = c;
    __syncthreads();
    for (int off = 512; off > 0; off >>= 1) {
        if (t < off) s[t] += s[t + off];
        __syncthreads();
    }
    if (t == 0) mode = (2 * s[0] > NROWS) ? 1 : 0;
    __syncthreads();
    int md = mode;
    for (int i = t; i < NROWS; i += 1024) {
        bool on = md ? (m[i] != 0) : (((const unsigned int*)m)[i] != 0u);
        g_mask[i] = on ? 1.0f : 0.0f;
    }
}

// ================= member-list build =================
__global__ void build_list_kernel(const int* __restrict__ seg,
                                  int* __restrict__ list, int stride,
                                  int* __restrict__ cnts, float* __restrict__ minv)
{
    int s = blockIdx.x;
    int t = threadIdx.x;
    int w = t >> 5, lane = t & 31;
    __shared__ int woff[32];
    __shared__ int wred[32];
    __shared__ int sbase, snext;
    if (t == 0) sbase = 0;
    int mcount = 0;
    __syncthreads();

    for (int c = 0; c < NROWS / 1024; c++) {
        int i = c * 1024 + t;
        bool pred = (seg[i] == s);
        bool mk = pred && (g_mask[i] > 0.5f);
        unsigned ball = __ballot_sync(0xffffffffu, pred);
        int wpre = __popc(ball & ((1u << lane) - 1u));
        if (lane == 0) woff[w] = __popc(ball);
        __syncthreads();
        if (w == 0) {
            int v = woff[lane];
            int sc = v;
            for (int o = 1; o < 32; o <<= 1) {
                int nb = __shfl_up_sync(0xffffffffu, sc, o);
                if (lane >= o) sc += nb;
            }
            woff[lane] = sbase + sc - v;
            if (lane == 31) snext = sbase + sc;
        }
        __syncthreads();
        if (pred) list[s * stride + woff[w] + wpre] = i | (mk ? 0x80000000 : 0);
        mcount += mk ? 1 : 0;
        if (t == 0) sbase = snext;
        __syncthreads();
    }

    for (int o = 16; o > 0; o >>= 1) mcount += __shfl_down_sync(0xffffffffu, mcount, o);
    if (lane == 0) wred[w] = mcount;
    __syncthreads();
    if (w == 0) {
        int v = wred[lane];
        for (int o = 16; o > 0; o >>= 1) v += __shfl_down_sync(0xffffffffu, v, o);
        if (lane == 0) {
            cnts[s] = sbase;
            minv[s] = 1.0f / fmaxf((float)v, 1e-6f);
        }
    }
}

__device__ __forceinline__ float gelu_tanh(float x) {
    float x3 = x * x * x;
    float inner = 0.7978845608028654f * (x + 0.044715f * x3);
    return 0.5f * x * (1.0f + tanhf(inner));
}

// ================= fp32 -> bf16 hi/lo splits =================
__device__ __forceinline__ void split2(float x, __nv_bfloat16& h, __nv_bfloat16& l) {
    h = __float2bfloat16(x);
    l = __float2bfloat16(x - __bfloat162float(h));
}

__global__ void split_local_kernel(const float* __restrict__ X) {
    int i4 = (blockIdx.x * 256 + threadIdx.x) * 4;
    float4 x = *(const float4*)(X + i4);
    __nv_bfloat16 h, l;
    split2(x.x, h, l); g_lhi[i4 + 0] = h; g_llo[i4 + 0] = l;
    split2(x.y, h, l); g_lhi[i4 + 1] = h; g_llo[i4 + 1] = l;
    split2(x.z, h, l); g_lhi[i4 + 2] = h; g_llo[i4 + 2] = l;
    split2(x.w, h, l); g_lhi[i4 + 3] = h; g_llo[i4 + 3] = l;
}

// transpose + split: out[(off+n)*K + k] = W[k*Ncols + n]
__global__ void wsplit_kernel(const float* __restrict__ W, int K, int Ncols,
                              __nv_bfloat16* __restrict__ hi, __nv_bfloat16* __restrict__ lo,
                              int off)
{
    int idx = blockIdx.x * 256 + threadIdx.x;
    if (idx >= K * Ncols) return;
    int n = idx / K, k = idx - n * K;
    float x = W[(size_t)k * Ncols + n];
    __nv_bfloat16 h, l;
    split2(x, h, l);
    hi[(size_t)(off + n) * K + k] = h;
    lo[(size_t)(off + n) * K + k] = l;
}

__global__ void split_y_kernel(const int* __restrict__ batch) {
    int i4 = (blockIdx.x * 256 + threadIdx.x) * 4;
    int r = i4 >> 10, c = i4 & 1023;
    int b = batch[r];
    float4 y = *(const float4*)(g_y + i4);
    float4 bm = *(const float4*)(g_bmean + b * YW + c);
    float s[4] = {y.x + bm.x, y.y + bm.y, y.z + bm.z, y.w + bm.w};
#pragma unroll
    for (int e = 0; e < 4; e++) {
        __nv_bfloat16 h, l;
        split2(s[e], h, l);
        g_yhi[i4 + e] = h;
        g_ylo[i4 + e] = l;
    }
}

// ================= mma.sync proj GEMM: [4096,256] x [256,1536] -> k|v|q =================
// BM=128, BN=128, BK=32, 256 threads = 8 warps (2x4), warp tile 64x32
__global__ void __launch_bounds__(256) proj_mma_kernel(
    const float* __restrict__ bk, const float* __restrict__ bv, const float* __restrict__ bq)
{
    __shared__ __align__(16) __nv_bfloat16 sAh[128 * SMS];
    __shared__ __align__(16) __nv_bfloat16 sAl[128 * SMS];
    __shared__ __align__(16) __nv_bfloat16 sBh[128 * SMS];
    __shared__ __align__(16) __nv_bfloat16 sBl[128 * SMS];

    int t = threadIdx.x, wid = t >> 5, lane = t & 31;
    int warp_m = wid & 1, warp_n = wid >> 1;
    int m0 = blockIdx.y * 128;
    int gn0 = blockIdx.x * 128;
    int sec = gn0 >> 9, wc = gn0 & 511;

    float acc[4][4][4];
#pragma unroll
    for (int i = 0; i < 4; i++)
#pragma unroll
        for (int j = 0; j < 4; j++)
#pragma unroll
            for (int e = 0; e < 4; e++) acc[i][j][e] = 0.f;

    uint32_t uAh = smem_u32(sAh), uAl = smem_u32(sAl);
    uint32_t uBh = smem_u32(sBh), uBl = smem_u32(sBl);

    int arow_a = warp_m * 64 + (lane & 15);
    int aksel  = (lane >> 4) * 8;
    int brow_b = warp_n * 32 + (lane & 7);
    int bksel  = ((lane >> 3) & 1) * 8;

    for (int ch = 0; ch < DIM / 32; ch++) {
        int k0 = ch * 32;
#pragma unroll
        for (int r = 0; r < 2; r++) {
            int idx = r * 256 + t;
            int row = idx >> 2, quad = idx & 3;
            const __nv_bfloat16* sa_h = g_lhi + (size_t)(m0 + row) * DIM + k0 + quad * 8;
            const __nv_bfloat16* sa_l = g_llo + (size_t)(m0 + row) * DIM + k0 + quad * 8;
            const __nv_bfloat16* sb_h = g_wthi + (size_t)(gn0 + row) * DIM + k0 + quad * 8;
            const __nv_bfloat16* sb_l = g_wtlo + (size_t)(gn0 + row) * DIM + k0 + quad * 8;
            *(uint4*)(sAh + row * SMS + quad * 8) = *(const uint4*)sa_h;
            *(uint4*)(sAl + row * SMS + quad * 8) = *(const uint4*)sa_l;
            *(uint4*)(sBh + row * SMS + quad * 8) = *(const uint4*)sb_h;
            *(uint4*)(sBl + row * SMS + quad * 8) = *(const uint4*)sb_l;
        }
        __syncthreads();

#pragma unroll
        for (int ko = 0; ko < 2; ko++) {
            uint32_t ah[4][4], al[4][4], bh[4][2], bl[4][2];
#pragma unroll
            for (int mt = 0; mt < 4; mt++) {
                uint32_t off = (uint32_t)(((arow_a + mt * 16) * SMS + ko * 16 + aksel) * 2);
                ldsm_x4(ah[mt], uAh + off);
                ldsm_x4(al[mt], uAl + off);
            }
#pragma unroll
            for (int nt = 0; nt < 4; nt++) {
                uint32_t off = (uint32_t)(((brow_b + nt * 8) * SMS + ko * 16 + bksel) * 2);
                ldsm_x2(bh[nt], uBh + off);
                ldsm_x2(bl[nt], uBl + off);
            }
#pragma unroll
            for (int mt = 0; mt < 4; mt++)
#pragma unroll
                for (int nt = 0; nt < 4; nt++) {
                    mma_bf16(acc[mt][nt], ah[mt], bh[nt]);
                    mma_bf16(acc[mt][nt], ah[mt], bl[nt]);
                    mma_bf16(acc[mt][nt], al[mt], bh[nt]);
                }
        }
        __syncthreads();
    }

    const float* bias = (sec == 0) ? bk : ((sec == 1) ? bv : bq);
    float* C = (sec == 0) ? g_k : ((sec == 1) ? g_v : g_q);
    int act = (sec != 1);
    int gid = lane >> 2, tig = lane & 3;

#pragma unroll
    for (int mt = 0; mt < 4; mt++) {
        int row = m0 + warp_m * 64 + mt * 16 + gid;
#pragma unroll
        for (int nt = 0; nt < 4; nt++) {
            int colg = wc + warp_n * 32 + nt * 8 + tig * 2;
            float b0 = bias[colg], b1 = bias[colg + 1];
            float v0 = acc[mt][nt][0] + b0, v1 = acc[mt][nt][1] + b1;
            float v2 = acc[mt][nt][2] + b0, v3 = acc[mt][nt][3] + b1;
            if (act) { v0 = gelu_tanh(v0); v1 = gelu_tanh(v1); v2 = gelu_tanh(v2); v3 = gelu_tanh(v3); }
            *(float2*)(C + (size_t)row * DFF + colg)       = make_float2(v0, v1);
            *(float2*)(C + (size_t)(row + 8) * DFF + colg) = make_float2(v2, v3);
        }
    }
}

// ================= mma.sync out GEMM: [4096,1024] x [1024,256] -> out =================
// BM=64, BN=128, BK=32, 8 warps (2x4), warp tile 32x32
__global__ void __launch_bounds__(256) out_mma_kernel(float* __restrict__ outp)
{
    __shared__ __align__(16) __nv_bfloat16 sAh[64 * SMS];
    __shared__ __align__(16) __nv_bfloat16 sAl[64 * SMS];
    __shared__ __align__(16) __nv_bfloat16 sBh[128 * SMS];
    __shared__ __align__(16) __nv_bfloat16 sBl[128 * SMS];

    int t = threadIdx.x, wid = t >> 5, lane = t & 31;
    int warp_m = wid & 1, warp_n = wid >> 1;
    int m0 = blockIdx.y * 64;
    int n0 = blockIdx.x * 128;

    float acc[2][4][4];
#pragma unroll
    for (int i = 0; i < 2; i++)
#pragma unroll
        for (int j = 0; j < 4; j++)
#pragma unroll
            for (int e = 0; e < 4; e++) acc[i][j][e] = 0.f;

    uint32_t uAh = smem_u32(sAh), uAl = smem_u32(sAl);
    uint32_t uBh = smem_u32(sBh), uBl = smem_u32(sBl);

    int arow_a = warp_m * 32 + (lane & 15);
    int aksel  = (lane >> 4) * 8;
    int brow_b = warp_n * 32 + (lane & 7);
    int bksel  = ((lane >> 3) & 1) * 8;

    for (int ch = 0; ch < YW / 32; ch++) {
        int k0 = ch * 32;
        {
            int idx = t;                       // A: 64 rows x 4 quads = 256
            int row = idx >> 2, quad = idx & 3;
            *(uint4*)(sAh + row * SMS + quad * 8) =
                *(const uint4*)(g_yhi + (size_t)(m0 + row) * YW + k0 + quad * 8);
            *(uint4*)(sAl + row * SMS + quad * 8) =
                *(const uint4*)(g_ylo + (size_t)(m0 + row) * YW + k0 + quad * 8);
        }
#pragma unroll
        for (int r = 0; r < 2; r++) {          // B: 128 rows x 4 quads = 512
            int idx = r * 256 + t;
            int row = idx >> 2, quad = idx & 3;
            *(uint4*)(sBh + row * SMS + quad * 8) =
                *(const uint4*)(g_wohi + (size_t)(n0 + row) * YW + k0 + quad * 8);
            *(uint4*)(sBl + row * SMS + quad * 8) =
                *(const uint4*)(g_wolo + (size_t)(n0 + row) * YW + k0 + quad * 8);
        }
        __syncthreads();

#pragma unroll
        for (int ko = 0; ko < 2; ko++) {
            uint32_t ah[2][4], al[2][4], bh[4][2], bl[4][2];
#pragma unroll
            for (int mt = 0; mt < 2; mt++) {
                uint32_t off = (uint32_t)(((arow_a + mt * 16) * SMS + ko * 16 + aksel) * 2);
                ldsm_x4(ah[mt], uAh + off);
                ldsm_x4(al[mt], uAl + off);
            }
#pragma unroll
            for (int nt = 0; nt < 4; nt++) {
                uint32_t off = (uint32_t)(((brow_b + nt * 8) * SMS + ko * 16 + bksel) * 2);
                ldsm_x2(bh[nt], uBh + off);
                ldsm_x2(bl[nt], uBl + off);
            }
#pragma unroll
            for (int mt = 0; mt < 2; mt++)
#pragma unroll
                for (int nt = 0; nt < 4; nt++) {
                    mma_bf16(acc[mt][nt], ah[mt], bh[nt]);
                    mma_bf16(acc[mt][nt], ah[mt], bl[nt]);
                    mma_bf16(acc[mt][nt], al[mt], bh[nt]);
                }
        }
        __syncthreads();
    }

    int gid = lane >> 2, tig = lane & 3;
#pragma unroll
    for (int mt = 0; mt < 2; mt++) {
        int row = m0 + warp_m * 32 + mt * 16 + gid;
#pragma unroll
        for (int nt = 0; nt < 4; nt++) {
            int col = n0 + warp_n * 32 + nt * 8 + tig * 2;
            *(float2*)(outp + (size_t)row * DIM + col) =
                make_float2(acc[mt][nt][0], acc[mt][nt][1]);
            *(float2*)(outp + (size_t)(row + 8) * DIM + col) =
                make_float2(acc[mt][nt][2], acc[mt][nt][3]);
        }
    }
}

// ================= per-batch masked sum of local rows =================
__global__ void batch_xsum_kernel(const float* __restrict__ local,
                                  const int* __restrict__ list,
                                  const int* __restrict__ cnts)
{
    int b   = blockIdx.x;
    int col = blockIdx.y * 128 + threadIdx.x;
    const int* L = list + b * BA_STRIDE;
    int n = cnts[b];
    float a0 = 0.f, a1 = 0.f, a2 = 0.f, a3 = 0.f;
    int m = 0;
    for (; m + 4 <= n; m += 4) {
        int e0 = L[m], e1 = L[m + 1], e2 = L[m + 2], e3 = L[m + 3];
        if (e0 < 0) a0 += local[(size_t)(e0 & 0x7fffffff) * DIM + col];
        if (e1 < 0) a1 += local[(size_t)(e1 & 0x7fffffff) * DIM + col];
        if (e2 < 0) a2 += local[(size_t)(e2 & 0x7fffffff) * DIM + col];
        if (e3 < 0) a3 += local[(size_t)(e3 & 0x7fffffff) * DIM + col];
    }
    for (; m < n; m++) {
        int e = L[m];
        if (e < 0) a0 += local[(size_t)(e & 0x7fffffff) * DIM + col];
    }
    g_xsum[b * DIM + col] = a0 + a1 + a2 + a3;
}

__global__ void bmean_kernel(const float* __restrict__ W_bias,
                             const float* __restrict__ b_bias,
                             const float* __restrict__ minv)
{
    __shared__ float xs[DIM];
    int b = blockIdx.x;
    int j = blockIdx.y * 128 + threadIdx.x;
    for (int k = threadIdx.x; k < DIM; k += 128) xs[k] = g_xsum[b * DIM + k];
    __syncthreads();
    float inv = minv[b];
    float acc = 0.f;
#pragma unroll 8
    for (int k = 0; k < DIM; k++) acc += xs[k] * W_bias[(size_t)k * YW + j];
    g_bmean[b * YW + j] = acc * inv + b_bias[j];
}

// ================= fused segment outer-product mean + apply =================
__global__ void seg_kernel(const float* __restrict__ kmat,
                           const float* __restrict__ vmat,
                           const float* __restrict__ qmat,
                           const int* __restrict__ list,
                           const int* __restrict__ cnts,
                           const float* __restrict__ minv,
                           float* __restrict__ y,
                           int stride, int col_off)
{
    int c = blockIdx.x;
    int h = blockIdx.y;
    int t = threadIdx.x;
    const int* L = list + c * stride;
    int n = cnts[c];
    float inv = minv[c];

    __shared__ __align__(16) float sm1[64 * 68];
    __shared__ __align__(16) float sm2[64 * 68];

    int ty = t >> 4, tx = t & 15;
    int mloc = t >> 2;
    int part = t & 3;

    float acc[4][4];
#pragma unroll
    for (int i = 0; i < 4; i++)
#pragma unroll
        for (int j = 0; j < 4; j++) acc[i][j] = 0.f;

    int nchunks = (n + 63) >> 6;

    for (int ch = 0; ch < nchunks; ch++) {
        int mrow = ch * 64 + mloc;
        float4 kq[4], vq[4];
        if (mrow < n) {
            int e = L[mrow];
            int i = e & 0x7fffffff;
            float mkf = (e < 0) ? 1.f : 0.f;
            const float4* kp = (const float4*)(kmat + (size_t)i * DFF + h * DHEAD + part * 16);
            const float4* vp = (const float4*)(vmat + (size_t)i * DFF + h * DHEAD + part * 16);
#pragma unroll
            for (int j = 0; j < 4; j++) {
                float4 kk = kp[j];
                kq[j] = make_float4(kk.x * mkf, kk.y * mkf, kk.z * mkf, kk.w * mkf);
                vq[j] = vp[j];
            }
        } else {
#pragma unroll
            for (int j = 0; j < 4; j++) {
                kq[j] = make_float4(0.f, 0.f, 0.f, 0.f);
                vq[j] = make_float4(0.f, 0.f, 0.f, 0.f);
            }
        }
#pragma unroll
        for (int j = 0; j < 4; j++) {
            *(float4*)(sm1 + mloc * 68 + part * 16 + j * 4) = kq[j];
            *(float4*)(sm2 + mloc * 68 + part * 16 + j * 4) = vq[j];
        }
        __syncthreads();

#pragma unroll 4
        for (int m = 0; m < 64; m++) {
            float4 af = *(const float4*)(sm1 + m * 68 + ty * 4);
            float4 bf = *(const float4*)(sm2 + m * 68 + tx * 4);
            acc[0][0] += af.x * bf.x; acc[0][1] += af.x * bf.y;
            acc[0][2] += af.x * bf.z; acc[0][3] += af.x * bf.w;
            acc[1][0] += af.y * bf.x; acc[1][1] += af.y * bf.y;
            acc[1][2] += af.y * bf.z; acc[1][3] += af.y * bf.w;
            acc[2][0] += af.z * bf.x; acc[2][1] += af.z * bf.y;
            acc[2][2] += af.z * bf.z; acc[2][3] += af.z * bf.w;
            acc[3][0] += af.w * bf.x; acc[3][1] += af.w * bf.y;
            acc[3][2] += af.w * bf.z; acc[3][3] += af.w * bf.w;
        }
        __syncthreads();
    }

#pragma unroll
    for (int i = 0; i < 4; i++)
#pragma unroll
        for (int j = 0; j < 4; j++)
            sm1[(ty * 4 + i) * 68 + tx * 4 + j] = acc[i][j] * inv;
    __syncthreads();

    for (int ch = 0; ch < nchunks; ch++) {
        int mrow = ch * 64 + mloc;
        float4 qq[4];
        if (mrow < n) {
            int i = L[mrow] & 0x7fffffff;
            const float4* qp = (const float4*)(qmat + (size_t)i * DFF + h * DHEAD + part * 16);
#pragma unroll
            for (int j = 0; j < 4; j++) qq[j] = qp[j];
        } else {
#pragma unroll
            for (int j = 0; j < 4; j++) qq[j] = make_float4(0.f, 0.f, 0.f, 0.f);
        }
#pragma unroll
        for (int j = 0; j < 4; j++)
            *(float4*)(sm2 + mloc * 68 + part * 16 + j * 4) = qq[j];
        __syncthreads();

        float o[4][4];
#pragma unroll
        for (int i = 0; i < 4; i++)
#pragma unroll
            for (int j = 0; j < 4; j++) o[i][j] = 0.f;

#pragma unroll 8
        for (int b = 0; b < 64; b += 4) {
#pragma unroll
            for (int i = 0; i < 4; i++) {
                float4 qf = *(const float4*)(sm2 + (ty * 4 + i) * 68 + b);
#pragma unroll
                for (int j = 0; j < 4; j++) {
                    float4 af = *(const float4*)(sm1 + (tx * 4 + j) * 68 + b);
                    o[i][j] += qf.x * af.x + qf.y * af.y + qf.z * af.z + qf.w * af.w;
                }
            }
        }

#pragma unroll
        for (int i = 0; i < 4; i++) {
            int mm = ch * 64 + ty * 4 + i;
            if (mm < n) {
                int irow = L[mm] & 0x7fffffff;
                float4 ov = make_float4(o[i][0], o[i][1], o[i][2], o[i][3]);
                *(float4*)(y + (size_t)irow * YW + h * 128 + col_off + tx * 4) = ov;
            }
        }
        __syncthreads();
    }
}

// ================= launch =================
extern "C" void kernel_launch(void* const* d_in, const int* in_sizes, int n_in,
                              void* d_out, int out_size)
{
    const float* local   = (const float*)d_in[0];
    const int*   chain   = (const int*)  d_in[1];
    const int*   batch   = (const int*)  d_in[2];
    const void*  mask    = d_in[3];
    const float* W_key   = (const float*)d_in[4];
    const float* b_key   = (const float*)d_in[5];
    const float* W_value = (const float*)d_in[6];
    const float* b_value = (const float*)d_in[7];
    const float* W_query = (const float*)d_in[8];
    const float* b_query = (const float*)d_in[9];
    const float* W_bias  = (const float*)d_in[10];
    const float* b_bias  = (const float*)d_in[11];
    const float* W_out   = (const float*)d_in[12];
    float* out = (float*)d_out;

    float *gk, *gv, *gq, *gy;
    int *glc, *glb, *gcc, *gcb;
    float *gmc, *gmb;
    __nv_bfloat16 *wth, *wtl, *woh, *wol;
    cudaGetSymbolAddress((void**)&gk,  g_k);
    cudaGetSymbolAddress((void**)&gv,  g_v);
    cudaGetSymbolAddress((void**)&gq,  g_q);
    cudaGetSymbolAddress((void**)&gy,  g_y);
    cudaGetSymbolAddress((void**)&glc, g_list_chain);
    cudaGetSymbolAddress((void**)&glb, g_list_batch);
    cudaGetSymbolAddress((void**)&gcc, g_cnt_chain);
    cudaGetSymbolAddress((void**)&gcb, g_cnt_batch);
    cudaGetSymbolAddress((void**)&gmc, g_minv_chain);
    cudaGetSymbolAddress((void**)&gmb, g_minv_batch);
    cudaGetSymbolAddress((void**)&wth, g_wthi);
    cudaGetSymbolAddress((void**)&wtl, g_wtlo);
    cudaGetSymbolAddress((void**)&woh, g_wohi);
    cudaGetSymbolAddress((void**)&wol, g_wolo);

    mask_kernel<<<1, 1024>>>((const unsigned char*)mask);

    build_list_kernel<<<NCHAIN, 1024>>>(chain, glc, CH_STRIDE, gcc, gmc);
    build_list_kernel<<<NBATCH, 1024>>>(batch, glb, BA_STRIDE, gcb, gmb);

    split_local_kernel<<<NROWS * DIM / 1024, 256>>>(local);
    wsplit_kernel<<<(DIM * DFF + 255) / 256, 256>>>(W_key,   DIM, DFF, wth, wtl, 0);
    wsplit_kernel<<<(DIM * DFF + 255) / 256, 256>>>(W_value, DIM, DFF, wth, wtl, DFF);
    wsplit_kernel<<<(DIM * DFF + 255) / 256, 256>>>(W_query, DIM, DFF, wth, wtl, 2 * DFF);
    wsplit_kernel<<<(YW * DIM + 255) / 256, 256>>>(W_out,    YW,  DIM, woh, wol, 0);

    proj_mma_kernel<<<dim3(1536 / 128, NROWS / 128), 256>>>(b_key, b_value, b_query);

    batch_xsum_kernel<<<dim3(NBATCH, DIM / 128), 128>>>(local, glb, gcb);
    bmean_kernel<<<dim3(NBATCH, YW / 128), 128>>>(W_bias, b_bias, gmb);

    seg_kernel<<<dim3(NCHAIN, NHEAD), 256>>>(gk, gv, gq, glc, gcc, gmc, gy, CH_STRIDE, 0);
    seg_kernel<<<dim3(NBATCH, NHEAD), 256>>>(gk, gv, gq, glb, gcb, gmb, gy, BA_STRIDE, DHEAD);

    split_y_kernel<<<NROWS * YW / 1024, 256>>>(batch);

    out_mma_kernel<<<dim3(DIM / 128, NROWS / 64), 256>>>(out);
}

// round 6
// speedup vs baseline: 3.5002x; 1.2422x over previous
#include <cuda_runtime.h>
#include <cuda_bf16.h>
#include <cstdint>

#define NROWS 4096
#define DIM 256
#define DFF 512
#define NHEAD 8
#define DHEAD 64
#define NCHAIN 64
#define NBATCH 8
#define YW 1024
#define CH_STRIDE 256
#define BA_STRIDE 1024

// ================= mma.sync helpers =================
__device__ __forceinline__ uint32_t smem_u32(const void* p) {
    uint32_t a;
    asm("{ .reg .u64 t; cvta.to.shared.u64 t, %1; cvt.u32.u64 %0, t; }" : "=r"(a) : "l"(p));
    return a;
}
__device__ __forceinline__ void mma_bf16(float* c, const uint32_t* a, const uint32_t* b) {
    asm volatile(
        "mma.sync.aligned.m16n8k16.row.col.f32.bf16.bf16.f32 "
        "{%0,%1,%2,%3}, {%4,%5,%6,%7}, {%8,%9}, {%0,%1,%2,%3};"
        : "+f"(c[0]), "+f"(c[1]), "+f"(c[2]), "+f"(c[3])
        : "r"(a[0]), "r"(a[1]), "r"(a[2]), "r"(a[3]), "r"(b[0]), "r"(b[1]));
}
__device__ __forceinline__ void ldsm_x4(uint32_t* r, uint32_t addr) {
    asm volatile("ldmatrix.sync.aligned.m8n8.x4.shared.b16 {%0,%1,%2,%3}, [%4];"
                 : "=r"(r[0]), "=r"(r[1]), "=r"(r[2]), "=r"(r[3]) : "r"(addr));
}
__device__ __forceinline__ void ldsm_x2(uint32_t* r, uint32_t addr) {
    asm volatile("ldmatrix.sync.aligned.m8n8.x2.shared.b16 {%0,%1}, [%2];"
                 : "=r"(r[0]), "=r"(r[1]) : "r"(addr));
}

#define SMS 40   // smem row stride in bf16 (80B rows -> conflict-free ldmatrix)

// ================= scratch =================
__device__ float g_k[NROWS * DFF];
__device__ float g_v[NROWS * DFF];
__device__ float g_q[NROWS * DFF];
__device__ float g_xsum[NBATCH * DIM];
__device__ float g_bmean[NBATCH * YW];
__device__ float g_mask[NROWS];

__device__ __nv_bfloat16 g_lhi[NROWS * DIM];
__device__ __nv_bfloat16 g_llo[NROWS * DIM];
__device__ __nv_bfloat16 g_wthi[3 * DFF * DIM];
__device__ __nv_bfloat16 g_wtlo[3 * DFF * DIM];
__device__ __nv_bfloat16 g_yhi[NROWS * YW];
__device__ __nv_bfloat16 g_ylo[NROWS * YW];
__device__ __nv_bfloat16 g_wohi[DIM * YW];
__device__ __nv_bfloat16 g_wolo[DIM * YW];

__device__ int   g_list_chain[NCHAIN * CH_STRIDE];
__device__ int   g_list_batch[NBATCH * BA_STRIDE];
__device__ int   g_cnt_chain[NCHAIN];
__device__ int   g_cnt_batch[NBATCH];
__device__ float g_minv_chain[NCHAIN];
__device__ float g_minv_batch[NBATCH];

// ================= mask detect + expand =================
__global__ void mask_kernel(const unsigned char* __restrict__ m) {
    __shared__ int s[1024];
    __shared__ int mode;
    int t = threadIdx.x;
    int c = 0;
    for (int i = t; i < NROWS; i += 1024) c += (m[i] != 0);
    s[t] = c;
    __syncthreads();
    for (int off = 512; off > 0; off >>= 1) {
        if (t < off) s[t] += s[t + off];
        __syncthreads();
    }
    if (t == 0) mode = (2 * s[0] > NROWS) ? 1 : 0;
    __syncthreads();
    int md = mode;
    for (int i = t; i < NROWS; i += 1024) {
        bool on = md ? (m[i] != 0) : (((const unsigned int*)m)[i] != 0u);
        g_mask[i] = on ? 1.0f : 0.0f;
    }
}

// ================= member-list build =================
__global__ void build_list_kernel(const int* __restrict__ seg,
                                  int* __restrict__ list, int stride,
                                  int* __restrict__ cnts, float* __restrict__ minv)
{
    int s = blockIdx.x;
    int t = threadIdx.x;
    int w = t >> 5, lane = t & 31;
    __shared__ int woff[32];
    __shared__ int wred[32];
    __shared__ int sbase, snext;
    if (t == 0) sbase = 0;
    int mcount = 0;
    __syncthreads();

    for (int c = 0; c < NROWS / 1024; c++) {
        int i = c * 1024 + t;
        bool pred = (seg[i] == s);
        bool mk = pred && (g_mask[i] > 0.5f);
        unsigned ball = __ballot_sync(0xffffffffu, pred);
        int wpre = __popc(ball & ((1u << lane) - 1u));
        if (lane == 0) woff[w] = __popc(ball);
        __syncthreads();
        if (w == 0) {
            int v = woff[lane];
            int sc = v;
            for (int o = 1; o < 32; o <<= 1) {
                int nb = __shfl_up_sync(0xffffffffu, sc, o);
                if (lane >= o) sc += nb;
            }
            woff[lane] = sbase + sc - v;
            if (lane == 31) snext = sbase + sc;
        }
        __syncthreads();
        if (pred) list[s * stride + woff[w] + wpre] = i | (mk ? 0x80000000 : 0);
        mcount += mk ? 1 : 0;
        if (t == 0) sbase = snext;
        __syncthreads();
    }

    for (int o = 16; o > 0; o >>= 1) mcount += __shfl_down_sync(0xffffffffu, mcount, o);
    if (lane == 0) wred[w] = mcount;
    __syncthreads();
    if (w == 0) {
        int v = wred[lane];
        for (int o = 16; o > 0; o >>= 1) v += __shfl_down_sync(0xffffffffu, v, o);
        if (lane == 0) {
            cnts[s] = sbase;
            minv[s] = 1.0f / fmaxf((float)v, 1e-6f);
        }
    }
}

__device__ __forceinline__ float gelu_tanh(float x) {
    float x3 = x * x * x;
    float inner = 0.7978845608028654f * (x + 0.044715f * x3);
    return 0.5f * x * (1.0f + tanhf(inner));
}

__device__ __forceinline__ void split2(float x, __nv_bfloat16& h, __nv_bfloat16& l) {
    h = __float2bfloat16(x);
    l = __float2bfloat16(x - __bfloat162float(h));
}

// ================= split local rows =================
__global__ void split_local_kernel(const float* __restrict__ X) {
    int i4 = (blockIdx.x * 256 + threadIdx.x) * 4;
    float4 x = *(const float4*)(X + i4);
    __nv_bfloat16 h, l;
    split2(x.x, h, l); g_lhi[i4 + 0] = h; g_llo[i4 + 0] = l;
    split2(x.y, h, l); g_lhi[i4 + 1] = h; g_llo[i4 + 1] = l;
    split2(x.z, h, l); g_lhi[i4 + 2] = h; g_llo[i4 + 2] = l;
    split2(x.w, h, l); g_lhi[i4 + 3] = h; g_llo[i4 + 3] = l;
}

// ================= all-weight tiled transpose + split =================
// z=0,1,2: W_{key,value,query} [256,512] -> g_wt{hi,lo}[(z*512+n)*256+k]
// z=3:     W_out [1024,256]    -> g_wo{hi,lo}[n*1024+k]
__global__ void wtsplit_kernel(const float* __restrict__ Wk, const float* __restrict__ Wv,
                               const float* __restrict__ Wq, const float* __restrict__ Wo)
{
    __shared__ float tile[32][33];
    int z = blockIdx.z;
    const float* W;
    int K, N, roff;
    __nv_bfloat16 *hi, *lo;
    if (z == 0)      { W = Wk; K = DIM; N = DFF; hi = g_wthi; lo = g_wtlo; roff = 0; }
    else if (z == 1) { W = Wv; K = DIM; N = DFF; hi = g_wthi; lo = g_wtlo; roff = DFF; }
    else if (z == 2) { W = Wq; K = DIM; N = DFF; hi = g_wthi; lo = g_wtlo; roff = 2 * DFF; }
    else             { W = Wo; K = YW;  N = DIM; hi = g_wohi; lo = g_wolo; roff = 0; }

    int nx0 = blockIdx.x * 32, ky0 = blockIdx.y * 32;
    if (nx0 >= N || ky0 >= K) return;
    int tx = threadIdx.x, ty = threadIdx.y;  // (32, 8)

#pragma unroll
    for (int r = 0; r < 4; r++) {
        int k = ky0 + ty + r * 8;
        tile[ty + r * 8][tx] = W[(size_t)k * N + nx0 + tx];
    }
    __syncthreads();
#pragma unroll
    for (int r = 0; r < 4; r++) {
        int n = nx0 + ty + r * 8;
        float x = tile[tx][ty + r * 8];
        __nv_bfloat16 h, l;
        split2(x, h, l);
        hi[(size_t)(roff + n) * K + ky0 + tx] = h;
        lo[(size_t)(roff + n) * K + ky0 + tx] = l;
    }
}

// ================= proj GEMM: [4096,256] x [256,1536] -> k|v|q (double-buffered) =================
#define PROJ_AS (128 * SMS)
#define PROJ_SMEM (8 * PROJ_AS * 2)
__global__ void __launch_bounds__(256) proj_mma_kernel(
    const float* __restrict__ bk, const float* __restrict__ bv, const float* __restrict__ bq)
{
    extern __shared__ __nv_bfloat16 smp[];
    __nv_bfloat16* sAh = smp;
    __nv_bfloat16* sAl = smp + 2 * PROJ_AS;
    __nv_bfloat16* sBh = smp + 4 * PROJ_AS;
    __nv_bfloat16* sBl = smp + 6 * PROJ_AS;

    int t = threadIdx.x, wid = t >> 5, lane = t & 31;
    int warp_m = wid & 1, warp_n = wid >> 1;
    int m0 = blockIdx.y * 128;
    int gn0 = blockIdx.x * 128;
    int sec = gn0 >> 9, wc = gn0 & 511;

    float acc[4][4][4];
#pragma unroll
    for (int i = 0; i < 4; i++)
#pragma unroll
        for (int j = 0; j < 4; j++)
#pragma unroll
            for (int e = 0; e < 4; e++) acc[i][j][e] = 0.f;

    uint32_t uAh = smem_u32(sAh), uAl = smem_u32(sAl);
    uint32_t uBh = smem_u32(sBh), uBl = smem_u32(sBl);

    int ldrow = t >> 2, ldq = t & 3;   // each thread: 2 rows (ldrow, ldrow+64), one quad
    int arow_a = warp_m * 64 + (lane & 15);
    int aksel  = (lane >> 4) * 8;
    int brow_b = warp_n * 32 + (lane & 7);
    int bksel  = ((lane >> 3) & 1) * 8;

    uint4 rAh[2], rAl[2], rBh[2], rBl[2];

#define PROJ_LOAD(k0_) do { \
    _Pragma("unroll") \
    for (int r = 0; r < 2; r++) { \
        int row = ldrow + r * 64; \
        rAh[r] = *(const uint4*)(g_lhi + (size_t)(m0 + row) * DIM + (k0_) + ldq * 8); \
        rAl[r] = *(const uint4*)(g_llo + (size_t)(m0 + row) * DIM + (k0_) + ldq * 8); \
        rBh[r] = *(const uint4*)(g_wthi + (size_t)(gn0 + row) * DIM + (k0_) + ldq * 8); \
        rBl[r] = *(const uint4*)(g_wtlo + (size_t)(gn0 + row) * DIM + (k0_) + ldq * 8); \
    } } while (0)

#define PROJ_STORE(st_) do { \
    _Pragma("unroll") \
    for (int r = 0; r < 2; r++) { \
        int row = ldrow + r * 64; \
        *(uint4*)(sAh + (st_) * PROJ_AS + row * SMS + ldq * 8) = rAh[r]; \
        *(uint4*)(sAl + (st_) * PROJ_AS + row * SMS + ldq * 8) = rAl[r]; \
        *(uint4*)(sBh + (st_) * PROJ_AS + row * SMS + ldq * 8) = rBh[r]; \
        *(uint4*)(sBl + (st_) * PROJ_AS + row * SMS + ldq * 8) = rBl[r]; \
    } } while (0)

    PROJ_LOAD(0);
    PROJ_STORE(0);
    __syncthreads();

    const int NCH = DIM / 32;  // 8
    for (int ch = 0; ch < NCH; ch++) {
        int cur = ch & 1;
        if (ch + 1 < NCH) PROJ_LOAD((ch + 1) * 32);
        uint32_t so = (uint32_t)(cur * PROJ_AS * 2);
#pragma unroll
        for (int ko = 0; ko < 2; ko++) {
            uint32_t ah[4][4], al[4][4], bh[4][2], bl[4][2];
#pragma unroll
            for (int mt = 0; mt < 4; mt++) {
                uint32_t off = so + (uint32_t)(((arow_a + mt * 16) * SMS + ko * 16 + aksel) * 2);
                ldsm_x4(ah[mt], uAh + off);
                ldsm_x4(al[mt], uAl + off);
            }
#pragma unroll
            for (int nt = 0; nt < 4; nt++) {
                uint32_t off = so + (uint32_t)(((brow_b + nt * 8) * SMS + ko * 16 + bksel) * 2);
                ldsm_x2(bh[nt], uBh + off);
                ldsm_x2(bl[nt], uBl + off);
            }
#pragma unroll
            for (int mt = 0; mt < 4; mt++)
#pragma unroll
                for (int nt = 0; nt < 4; nt++) {
                    mma_bf16(acc[mt][nt], ah[mt], bh[nt]);
                    mma_bf16(acc[mt][nt], ah[mt], bl[nt]);
                    mma_bf16(acc[mt][nt], al[mt], bh[nt]);
                }
        }
        if (ch + 1 < NCH) {
            PROJ_STORE(cur ^ 1);
            __syncthreads();
        }
    }

    const float* bias = (sec == 0) ? bk : ((sec == 1) ? bv : bq);
    float* C = (sec == 0) ? g_k : ((sec == 1) ? g_v : g_q);
    int act = (sec != 1);
    int gid = lane >> 2, tig = lane & 3;

#pragma unroll
    for (int mt = 0; mt < 4; mt++) {
        int row = m0 + warp_m * 64 + mt * 16 + gid;
#pragma unroll
        for (int nt = 0; nt < 4; nt++) {
            int colg = wc + warp_n * 32 + nt * 8 + tig * 2;
            float b0 = bias[colg], b1 = bias[colg + 1];
            float v0 = acc[mt][nt][0] + b0, v1 = acc[mt][nt][1] + b1;
            float v2 = acc[mt][nt][2] + b0, v3 = acc[mt][nt][3] + b1;
            if (act) { v0 = gelu_tanh(v0); v1 = gelu_tanh(v1); v2 = gelu_tanh(v2); v3 = gelu_tanh(v3); }
            *(float2*)(C + (size_t)row * DFF + colg)       = make_float2(v0, v1);
            *(float2*)(C + (size_t)(row + 8) * DFF + colg) = make_float2(v2, v3);
        }
    }
}

// ================= out GEMM: [4096,1024] x [1024,256] -> out (double-buffered) =================
#define OUT_AS (64 * SMS)
#define OUT_BS (128 * SMS)
#define OUT_SMEM ((4 * OUT_AS + 4 * OUT_BS) * 2)
__global__ void __launch_bounds__(256) out_mma_kernel(float* __restrict__ outp)
{
    extern __shared__ __nv_bfloat16 smp[];
    __nv_bfloat16* sAh = smp;
    __nv_bfloat16* sAl = smp + 2 * OUT_AS;
    __nv_bfloat16* sBh = smp + 4 * OUT_AS;
    __nv_bfloat16* sBl = smp + 4 * OUT_AS + 2 * OUT_BS;

    int t = threadIdx.x, wid = t >> 5, lane = t & 31;
    int warp_m = wid & 1, warp_n = wid >> 1;
    int m0 = blockIdx.y * 64;
    int n0 = blockIdx.x * 128;

    float acc[2][4][4];
#pragma unroll
    for (int i = 0; i < 2; i++)
#pragma unroll
        for (int j = 0; j < 4; j++)
#pragma unroll
            for (int e = 0; e < 4; e++) acc[i][j][e] = 0.f;

    uint32_t uAh = smem_u32(sAh), uAl = smem_u32(sAl);
    uint32_t uBh = smem_u32(sBh), uBl = smem_u32(sBl);

    int ldrow = t >> 2, ldq = t & 3;
    int arow_a = warp_m * 32 + (lane & 15);
    int aksel  = (lane >> 4) * 8;
    int brow_b = warp_n * 32 + (lane & 7);
    int bksel  = ((lane >> 3) & 1) * 8;

    uint4 rAh, rAl, rBh[2], rBl[2];

#define OUT_LOAD(k0_) do { \
    rAh = *(const uint4*)(g_yhi + (size_t)(m0 + ldrow) * YW + (k0_) + ldq * 8); \
    rAl = *(const uint4*)(g_ylo + (size_t)(m0 + ldrow) * YW + (k0_) + ldq * 8); \
    _Pragma("unroll") \
    for (int r = 0; r < 2; r++) { \
        int row = ldrow + r * 64; \
        rBh[r] = *(const uint4*)(g_wohi + (size_t)(n0 + row) * YW + (k0_) + ldq * 8); \
        rBl[r] = *(const uint4*)(g_wolo + (size_t)(n0 + row) * YW + (k0_) + ldq * 8); \
    } } while (0)

#define OUT_STORE(st_) do { \
    *(uint4*)(sAh + (st_) * OUT_AS + ldrow * SMS + ldq * 8) = rAh; \
    *(uint4*)(sAl + (st_) * OUT_AS + ldrow * SMS + ldq * 8) = rAl; \
    _Pragma("unroll") \
    for (int r = 0; r < 2; r++) { \
        int row = ldrow + r * 64; \
        *(uint4*)(sBh + (st_) * OUT_BS + row * SMS + ldq * 8) = rBh[r]; \
        *(uint4*)(sBl + (st_) * OUT_BS + row * SMS + ldq * 8) = rBl[r]; \
    } } while (0)

    OUT_LOAD(0);
    OUT_STORE(0);
    __syncthreads();

    const int NCH = YW / 32;  // 32
    for (int ch = 0; ch < NCH; ch++) {
        int cur = ch & 1;
        if (ch + 1 < NCH) OUT_LOAD((ch + 1) * 32);
        uint32_t soA = (uint32_t)(cur * OUT_AS * 2);
        uint32_t soB = (uint32_t)(cur * OUT_BS * 2);
#pragma unroll
        for (int ko = 0; ko < 2; ko++) {
            uint32_t ah[2][4], al[2][4], bh[4][2], bl[4][2];
#pragma unroll
            for (int mt = 0; mt < 2; mt++) {
                uint32_t off = soA + (uint32_t)(((arow_a + mt * 16) * SMS + ko * 16 + aksel) * 2);
                ldsm_x4(ah[mt], uAh + off);
                ldsm_x4(al[mt], uAl + off);
            }
#pragma unroll
            for (int nt = 0; nt < 4; nt++) {
                uint32_t off = soB + (uint32_t)(((brow_b + nt * 8) * SMS + ko * 16 + bksel) * 2);
                ldsm_x2(bh[nt], uBh + off);
                ldsm_x2(bl[nt], uBl + off);
            }
#pragma unroll
            for (int mt = 0; mt < 2; mt++)
#pragma unroll
                for (int nt = 0; nt < 4; nt++) {
                    mma_bf16(acc[mt][nt], ah[mt], bh[nt]);
                    mma_bf16(acc[mt][nt], ah[mt], bl[nt]);
                    mma_bf16(acc[mt][nt], al[mt], bh[nt]);
                }
        }
        if (ch + 1 < NCH) {
            OUT_STORE(cur ^ 1);
            __syncthreads();
        }
    }

    int gid = lane >> 2, tig = lane & 3;
#pragma unroll
    for (int mt = 0; mt < 2; mt++) {
        int row = m0 + warp_m * 32 + mt * 16 + gid;
#pragma unroll
        for (int nt = 0; nt < 4; nt++) {
            int col = n0 + warp_n * 32 + nt * 8 + tig * 2;
            *(float2*)(outp + (size_t)row * DIM + col) =
                make_float2(acc[mt][nt][0], acc[mt][nt][1]);
            *(float2*)(outp + (size_t)(row + 8) * DIM + col) =
                make_float2(acc[mt][nt][2], acc[mt][nt][3]);
        }
    }
}

// ================= per-batch masked sum + bmean =================
__global__ void batch_xsum_kernel(const float* __restrict__ local,
                                  const int* __restrict__ list,
                                  const int* __restrict__ cnts)
{
    int b   = blockIdx.x;
    int col = blockIdx.y * 128 + threadIdx.x;
    const int* L = list + b * BA_STRIDE;
    int n = cnts[b];
    float a0 = 0.f, a1 = 0.f, a2 = 0.f, a3 = 0.f;
    int m = 0;
    for (; m + 4 <= n; m += 4) {
        int e0 = L[m], e1 = L[m + 1], e2 = L[m + 2], e3 = L[m + 3];
        if (e0 < 0) a0 += local[(size_t)(e0 & 0x7fffffff) * DIM + col];
        if (e1 < 0) a1 += local[(size_t)(e1 & 0x7fffffff) * DIM + col];
        if (e2 < 0) a2 += local[(size_t)(e2 & 0x7fffffff) * DIM + col];
        if (e3 < 0) a3 += local[(size_t)(e3 & 0x7fffffff) * DIM + col];
    }
    for (; m < n; m++) {
        int e = L[m];
        if (e < 0) a0 += local[(size_t)(e & 0x7fffffff) * DIM + col];
    }
    g_xsum[b * DIM + col] = a0 + a1 + a2 + a3;
}

__global__ void bmean_kernel(const float* __restrict__ W_bias,
                             const float* __restrict__ b_bias,
                             const float* __restrict__ minv)
{
    __shared__ float xs[DIM];
    int b = blockIdx.x;
    int j = blockIdx.y * 128 + threadIdx.x;
    for (int k = threadIdx.x; k < DIM; k += 128) xs[k] = g_xsum[b * DIM + k];
    __syncthreads();
    float inv = minv[b];
    float acc = 0.f;
#pragma unroll 8
    for (int k = 0; k < DIM; k++) acc += xs[k] * W_bias[(size_t)k * YW + j];
    g_bmean[b * YW + j] = acc * inv + b_bias[j];
}

// ================= combined seg kernel: chain + batch, fused bmean+split epilogue =================
// grid.x = NBATCH*NHEAD (first, heavy) + NCHAIN*NHEAD
__global__ void seg_all_kernel(const float* __restrict__ kmat,
                               const float* __restrict__ vmat,
                               const float* __restrict__ qmat,
                               const int* __restrict__ batchv)
{
    int bid = blockIdx.x;
    const int* L;
    int n, col_off, h;
    float inv;
    if (bid < NBATCH * NHEAD) {
        int c = bid >> 3; h = bid & 7;
        L = g_list_batch + c * BA_STRIDE;
        n = g_cnt_batch[c]; inv = g_minv_batch[c];
        col_off = DHEAD;
    } else {
        int idx = bid - NBATCH * NHEAD;
        int c = idx >> 3; h = idx & 7;
        L = g_list_chain + c * CH_STRIDE;
        n = g_cnt_chain[c]; inv = g_minv_chain[c];
        col_off = 0;
    }
    int t = threadIdx.x;

    __shared__ __align__(16) float sm1[64 * 68];
    __shared__ __align__(16) float sm2[64 * 68];

    int ty = t >> 4, tx = t & 15;
    int mloc = t >> 2;
    int part = t & 3;

    float acc[4][4];
#pragma unroll
    for (int i = 0; i < 4; i++)
#pragma unroll
        for (int j = 0; j < 4; j++) acc[i][j] = 0.f;

    int nchunks = (n + 63) >> 6;

    for (int ch = 0; ch < nchunks; ch++) {
        int mrow = ch * 64 + mloc;
        float4 kq[4], vq[4];
        if (mrow < n) {
            int e = L[mrow];
            int i = e & 0x7fffffff;
            float mkf = (e < 0) ? 1.f : 0.f;
            const float4* kp = (const float4*)(kmat + (size_t)i * DFF + h * DHEAD + part * 16);
            const float4* vp = (const float4*)(vmat + (size_t)i * DFF + h * DHEAD + part * 16);
#pragma unroll
            for (int j = 0; j < 4; j++) {
                float4 kk = kp[j];
                kq[j] = make_float4(kk.x * mkf, kk.y * mkf, kk.z * mkf, kk.w * mkf);
                vq[j] = vp[j];
            }
        } else {
#pragma unroll
            for (int j = 0; j < 4; j++) {
                kq[j] = make_float4(0.f, 0.f, 0.f, 0.f);
                vq[j] = make_float4(0.f, 0.f, 0.f, 0.f);
            }
        }
#pragma unroll
        for (int j = 0; j < 4; j++) {
            *(float4*)(sm1 + mloc * 68 + part * 16 + j * 4) = kq[j];
            *(float4*)(sm2 + mloc * 68 + part * 16 + j * 4) = vq[j];
        }
        __syncthreads();

#pragma unroll 4
        for (int m = 0; m < 64; m++) {
            float4 af = *(const float4*)(sm1 + m * 68 + ty * 4);
            float4 bf = *(const float4*)(sm2 + m * 68 + tx * 4);
            acc[0][0] += af.x * bf.x; acc[0][1] += af.x * bf.y;
            acc[0][2] += af.x * bf.z; acc[0][3] += af.x * bf.w;
            acc[1][0] += af.y * bf.x; acc[1][1] += af.y * bf.y;
            acc[1][2] += af.y * bf.z; acc[1][3] += af.y * bf.w;
            acc[2][0] += af.z * bf.x; acc[2][1] += af.z * bf.y;
            acc[2][2] += af.z * bf.z; acc[2][3] += af.z * bf.w;
            acc[3][0] += af.w * bf.x; acc[3][1] += af.w * bf.y;
            acc[3][2] += af.w * bf.z; acc[3][3] += af.w * bf.w;
        }
        __syncthreads();
    }

#pragma unroll
    for (int i = 0; i < 4; i++)
#pragma unroll
        for (int j = 0; j < 4; j++)
            sm1[(ty * 4 + i) * 68 + tx * 4 + j] = acc[i][j] * inv;
    __syncthreads();

    int colbase = h * 128 + col_off + tx * 4;

    for (int ch = 0; ch < nchunks; ch++) {
        int mrow = ch * 64 + mloc;
        float4 qq[4];
        if (mrow < n) {
            int i = L[mrow] & 0x7fffffff;
            const float4* qp = (const float4*)(qmat + (size_t)i * DFF + h * DHEAD + part * 16);
#pragma unroll
            for (int j = 0; j < 4; j++) qq[j] = qp[j];
        } else {
#pragma unroll
            for (int j = 0; j < 4; j++) qq[j] = make_float4(0.f, 0.f, 0.f, 0.f);
        }
#pragma unroll
        for (int j = 0; j < 4; j++)
            *(float4*)(sm2 + mloc * 68 + part * 16 + j * 4) = qq[j];
        __syncthreads();

        float o[4][4];
#pragma unroll
        for (int i = 0; i < 4; i++)
#pragma unroll
            for (int j = 0; j < 4; j++) o[i][j] = 0.f;

#pragma unroll 8
        for (int b = 0; b < 64; b += 4) {
#pragma unroll
            for (int i = 0; i < 4; i++) {
                float4 qf = *(const float4*)(sm2 + (ty * 4 + i) * 68 + b);
#pragma unroll
                for (int j = 0; j < 4; j++) {
                    float4 af = *(const float4*)(sm1 + (tx * 4 + j) * 68 + b);
                    o[i][j] += qf.x * af.x + qf.y * af.y + qf.z * af.z + qf.w * af.w;
                }
            }
        }

#pragma unroll
        for (int i = 0; i < 4; i++) {
            int mm = ch * 64 + ty * 4 + i;
            if (mm < n) {
                int irow = L[mm] & 0x7fffffff;
                int bb = batchv[irow];
                float4 bm = *(const float4*)(g_bmean + (size_t)bb * YW + colbase);
                __nv_bfloat16 h0, l0, h1, l1, h2, l2, h3, l3;
                split2(o[i][0] + bm.x, h0, l0);
                split2(o[i][1] + bm.y, h1, l1);
                split2(o[i][2] + bm.z, h2, l2);
                split2(o[i][3] + bm.w, h3, l3);
                __nv_bfloat16* ph = g_yhi + (size_t)irow * YW + colbase;
                __nv_bfloat16* pl = g_ylo + (size_t)irow * YW + colbase;
                *(__nv_bfloat162*)(ph)     = __nv_bfloat162(h0, h1);
                *(__nv_bfloat162*)(ph + 2) = __nv_bfloat162(h2, h3);
                *(__nv_bfloat162*)(pl)     = __nv_bfloat162(l0, l1);
                *(__nv_bfloat162*)(pl + 2) = __nv_bfloat162(l2, l3);
            }
        }
        __syncthreads();
    }
}

// ================= launch =================
extern "C" void kernel_launch(void* const* d_in, const int* in_sizes, int n_in,
                              void* d_out, int out_size)
{
    const float* local   = (const float*)d_in[0];
    const int*   chain   = (const int*)  d_in[1];
    const int*   batch   = (const int*)  d_in[2];
    const void*  mask    = d_in[3];
    const float* W_key   = (const float*)d_in[4];
    const float* b_key   = (const float*)d_in[5];
    const float* W_value = (const float*)d_in[6];
    const float* b_value = (const float*)d_in[7];
    const float* W_query = (const float*)d_in[8];
    const float* b_query = (const float*)d_in[9];
    const float* W_bias  = (const float*)d_in[10];
    const float* b_bias  = (const float*)d_in[11];
    const float* W_out   = (const float*)d_in[12];
    float* out = (float*)d_out;

    float *gk, *gv, *gq;
    int *glc, *glb, *gcc, *gcb;
    float *gmc, *gmb;
    cudaGetSymbolAddress((void**)&gk,  g_k);
    cudaGetSymbolAddress((void**)&gv,  g_v);
    cudaGetSymbolAddress((void**)&gq,  g_q);
    cudaGetSymbolAddress((void**)&glc, g_list_chain);
    cudaGetSymbolAddress((void**)&glb, g_list_batch);
    cudaGetSymbolAddress((void**)&gcc, g_cnt_chain);
    cudaGetSymbolAddress((void**)&gcb, g_cnt_batch);
    cudaGetSymbolAddress((void**)&gmc, g_minv_chain);
    cudaGetSymbolAddress((void**)&gmb, g_minv_batch);

    static bool attr_done = false;
    if (!attr_done) {
        cudaFuncSetAttribute(proj_mma_kernel, cudaFuncAttributeMaxDynamicSharedMemorySize, PROJ_SMEM);
        cudaFuncSetAttribute(out_mma_kernel,  cudaFuncAttributeMaxDynamicSharedMemorySize, OUT_SMEM);
        attr_done = true;
    }

    mask_kernel<<<1, 1024>>>((const unsigned char*)mask);

    build_list_kernel<<<NCHAIN, 1024>>>(chain, glc, CH_STRIDE, gcc, gmc);
    build_list_kernel<<<NBATCH, 1024>>>(batch, glb, BA_STRIDE, gcb, gmb);

    split_local_kernel<<<NROWS * DIM / 1024, 256>>>(local);
    wtsplit_kernel<<<dim3(16, 32, 4), dim3(32, 8)>>>(W_key, W_value, W_query, W_out);

    batch_xsum_kernel<<<dim3(NBATCH, DIM / 128), 128>>>(local, glb, gcb);
    bmean_kernel<<<dim3(NBATCH, YW / 128), 128>>>(W_bias, b_bias, gmb);

    proj_mma_kernel<<<dim3(1536 / 128, NROWS / 128), 256, PROJ_SMEM>>>(b_key, b_value, b_query);

    seg_all_kernel<<<NBATCH * NHEAD + NCHAIN * NHEAD, 256>>>(gk, gv, gq, batch);

    out_mma_kernel<<<dim3(DIM / 128, NROWS / 64), 256, OUT_SMEM>>>(out);
}

// round 7
// speedup vs baseline: 4.2045x; 1.2012x over previous
#include <cuda_runtime.h>
#include <cuda_bf16.h>
#include <cstdint>

#define NROWS 4096
#define DIM 256
#define DFF 512
#define NHEAD 8
#define DHEAD 64
#define NCHAIN 64
#define NBATCH 8
#define YW 1024
#define CH_STRIDE 256
#define BA_STRIDE 1024

// ================= mma.sync / cp.async helpers =================
__device__ __forceinline__ uint32_t smem_u32(const void* p) {
    uint32_t a;
    asm("{ .reg .u64 t; cvta.to.shared.u64 t, %1; cvt.u32.u64 %0, t; }" : "=r"(a) : "l"(p));
    return a;
}
__device__ __forceinline__ void mma_bf16(float* c, const uint32_t* a, const uint32_t* b) {
    asm volatile(
        "mma.sync.aligned.m16n8k16.row.col.f32.bf16.bf16.f32 "
        "{%0,%1,%2,%3}, {%4,%5,%6,%7}, {%8,%9}, {%0,%1,%2,%3};"
        : "+f"(c[0]), "+f"(c[1]), "+f"(c[2]), "+f"(c[3])
        : "r"(a[0]), "r"(a[1]), "r"(a[2]), "r"(a[3]), "r"(b[0]), "r"(b[1]));
}
__device__ __forceinline__ void ldsm_x4(uint32_t* r, uint32_t addr) {
    asm volatile("ldmatrix.sync.aligned.m8n8.x4.shared.b16 {%0,%1,%2,%3}, [%4];"
                 : "=r"(r[0]), "=r"(r[1]), "=r"(r[2]), "=r"(r[3]) : "r"(addr));
}
__device__ __forceinline__ void ldsm_x2(uint32_t* r, uint32_t addr) {
    asm volatile("ldmatrix.sync.aligned.m8n8.x2.shared.b16 {%0,%1}, [%2];"
                 : "=r"(r[0]), "=r"(r[1]) : "r"(addr));
}
__device__ __forceinline__ void cp_async16(uint32_t saddr, const void* g) {
    asm volatile("cp.async.cg.shared.global [%0], [%1], 16;" :: "r"(saddr), "l"(g));
}
#define CP_COMMIT() asm volatile("cp.async.commit_group;" ::: "memory")
#define CP_WAIT1()  asm volatile("cp.async.wait_group 1;" ::: "memory")
#define CP_WAIT0()  asm volatile("cp.async.wait_group 0;" ::: "memory")

#define SMS 40   // smem row stride in bf16 (80B rows -> conflict-free ldmatrix, 16B aligned)

// ================= scratch =================
__device__ float g_k[NROWS * DFF];
__device__ float g_v[NROWS * DFF];
__device__ float g_q[NROWS * DFF];
__device__ float g_bmean[NBATCH * YW];
__device__ float g_mask[NROWS];

__device__ __nv_bfloat16 g_lhi[NROWS * DIM];
__device__ __nv_bfloat16 g_llo[NROWS * DIM];
__device__ __nv_bfloat16 g_wthi[3 * DFF * DIM];
__device__ __nv_bfloat16 g_wtlo[3 * DFF * DIM];
__device__ __nv_bfloat16 g_yhi[NROWS * YW];
__device__ __nv_bfloat16 g_ylo[NROWS * YW];
__device__ __nv_bfloat16 g_wohi[DIM * YW];
__device__ __nv_bfloat16 g_wolo[DIM * YW];

__device__ int   g_list_chain[NCHAIN * CH_STRIDE];
__device__ int   g_list_batch[NBATCH * BA_STRIDE];
__device__ int   g_cnt_chain[NCHAIN];
__device__ int   g_cnt_batch[NBATCH];
__device__ float g_minv_chain[NCHAIN];
__device__ float g_minv_batch[NBATCH];

// ================= mask detect + expand =================
__global__ void mask_kernel(const unsigned char* __restrict__ m) {
    __shared__ int s[1024];
    __shared__ int mode;
    int t = threadIdx.x;
    int c = 0;
    for (int i = t; i < NROWS; i += 1024) c += (m[i] != 0);
    s[t] = c;
    __syncthreads();
    for (int off = 512; off > 0; off >>= 1) {
        if (t < off) s[t] += s[t + off];
        __syncthreads();
    }
    if (t == 0) mode = (2 * s[0] > NROWS) ? 1 : 0;
    __syncthreads();
    int md = mode;
    for (int i = t; i < NROWS; i += 1024) {
        bool on = md ? (m[i] != 0) : (((const unsigned int*)m)[i] != 0u);
        g_mask[i] = on ? 1.0f : 0.0f;
    }
}

// ================= fused list build (chain+batch) + batch xsum + bmean =================
// grid.x = NBATCH (batch, heavy) + NCHAIN (chain), 1024 threads
__global__ void __launch_bounds__(1024) build_all_kernel(
    const int* __restrict__ chain, const int* __restrict__ batch,
    const float* __restrict__ local,
    const float* __restrict__ W_bias, const float* __restrict__ b_bias)
{
    int blk = blockIdx.x;
    bool isb = (blk < NBATCH);
    int s = isb ? blk : blk - NBATCH;
    const int* seg = isb ? batch : chain;
    int stride = isb ? BA_STRIDE : CH_STRIDE;
    int* list = isb ? g_list_batch : g_list_chain;
    int* cnts = isb ? g_cnt_batch : g_cnt_chain;
    float* minv = isb ? g_minv_batch : g_minv_chain;

    int t = threadIdx.x;
    int w = t >> 5, lane = t & 31;
    __shared__ int woff[32];
    __shared__ int wred[32];
    __shared__ int sbase, snext;
    __shared__ float sinv;
    __shared__ float xs4[4][DIM];
    __shared__ float xs[DIM];
    if (t == 0) sbase = 0;
    int mcount = 0;
    __syncthreads();

    for (int c = 0; c < NROWS / 1024; c++) {
        int i = c * 1024 + t;
        bool pred = (seg[i] == s);
        bool mk = pred && (g_mask[i] > 0.5f);
        unsigned ball = __ballot_sync(0xffffffffu, pred);
        int wpre = __popc(ball & ((1u << lane) - 1u));
        if (lane == 0) woff[w] = __popc(ball);
        __syncthreads();
        if (w == 0) {
            int v = woff[lane];
            int sc = v;
            for (int o = 1; o < 32; o <<= 1) {
                int nb = __shfl_up_sync(0xffffffffu, sc, o);
                if (lane >= o) sc += nb;
            }
            woff[lane] = sbase + sc - v;
            if (lane == 31) snext = sbase + sc;
        }
        __syncthreads();
        if (pred) list[s * stride + woff[w] + wpre] = i | (mk ? 0x80000000 : 0);
        mcount += mk ? 1 : 0;
        if (t == 0) sbase = snext;
        __syncthreads();
    }

    for (int o = 16; o > 0; o >>= 1) mcount += __shfl_down_sync(0xffffffffu, mcount, o);
    if (lane == 0) wred[w] = mcount;
    __syncthreads();
    if (w == 0) {
        int v = wred[lane];
        for (int o = 16; o > 0; o >>= 1) v += __shfl_down_sync(0xffffffffu, v, o);
        if (lane == 0) {
            cnts[s] = sbase;
            float iv = 1.0f / fmaxf((float)v, 1e-6f);
            minv[s] = iv;
            sinv = iv;
        }
    }
    __syncthreads();

    if (!isb) return;

    // ---- xsum: masked sum of local rows over this batch ----
    int n = sbase;
    int quarter = t >> 8, col = t & 255;
    float a = 0.f;
    const int* L = list + s * stride;
    for (int m = quarter; m < n; m += 4) {
        int e = L[m];
        if (e < 0) a += local[(size_t)(e & 0x7fffffff) * DIM + col];
    }
    xs4[quarter][col] = a;
    __syncthreads();
    if (t < DIM) xs[t] = (xs4[0][t] + xs4[1][t]) + (xs4[2][t] + xs4[3][t]);
    __syncthreads();

    // ---- bmean[s][j] = (xs/cnt) @ W_bias[:,j] + b_bias[j], j = t ----
    float inv = sinv;
    float acc = 0.f;
#pragma unroll 8
    for (int k = 0; k < DIM; k++) acc += xs[k] * W_bias[(size_t)k * YW + t];
    g_bmean[s * YW + t] = acc * inv + b_bias[t];
}

__device__ __forceinline__ float gelu_tanh(float x) {
    float x3 = x * x * x;
    float inner = 0.7978845608028654f * (x + 0.044715f * x3);
    return 0.5f * x * (1.0f + tanhf(inner));
}

__device__ __forceinline__ void split2(float x, __nv_bfloat16& h, __nv_bfloat16& l) {
    h = __float2bfloat16(x);
    l = __float2bfloat16(x - __bfloat162float(h));
}

// ================= split local rows =================
__global__ void split_local_kernel(const float* __restrict__ X) {
    int i4 = (blockIdx.x * 256 + threadIdx.x) * 4;
    float4 x = *(const float4*)(X + i4);
    __nv_bfloat16 h, l;
    split2(x.x, h, l); g_lhi[i4 + 0] = h; g_llo[i4 + 0] = l;
    split2(x.y, h, l); g_lhi[i4 + 1] = h; g_llo[i4 + 1] = l;
    split2(x.z, h, l); g_lhi[i4 + 2] = h; g_llo[i4 + 2] = l;
    split2(x.w, h, l); g_lhi[i4 + 3] = h; g_llo[i4 + 3] = l;
}

// ================= all-weight tiled transpose + split =================
__global__ void wtsplit_kernel(const float* __restrict__ Wk, const float* __restrict__ Wv,
                               const float* __restrict__ Wq, const float* __restrict__ Wo)
{
    __shared__ float tile[32][33];
    int z = blockIdx.z;
    const float* W;
    int K, N, roff;
    __nv_bfloat16 *hi, *lo;
    if (z == 0)      { W = Wk; K = DIM; N = DFF; hi = g_wthi; lo = g_wtlo; roff = 0; }
    else if (z == 1) { W = Wv; K = DIM; N = DFF; hi = g_wthi; lo = g_wtlo; roff = DFF; }
    else if (z == 2) { W = Wq; K = DIM; N = DFF; hi = g_wthi; lo = g_wtlo; roff = 2 * DFF; }
    else             { W = Wo; K = YW;  N = DIM; hi = g_wohi; lo = g_wolo; roff = 0; }

    int nx0 = blockIdx.x * 32, ky0 = blockIdx.y * 32;
    if (nx0 >= N || ky0 >= K) return;
    int tx = threadIdx.x, ty = threadIdx.y;  // (32, 8)

#pragma unroll
    for (int r = 0; r < 4; r++) {
        int k = ky0 + ty + r * 8;
        tile[ty + r * 8][tx] = W[(size_t)k * N + nx0 + tx];
    }
    __syncthreads();
#pragma unroll
    for (int r = 0; r < 4; r++) {
        int n = nx0 + ty + r * 8;
        float x = tile[tx][ty + r * 8];
        __nv_bfloat16 h, l;
        split2(x, h, l);
        hi[(size_t)(roff + n) * K + ky0 + tx] = h;
        lo[(size_t)(roff + n) * K + ky0 + tx] = l;
    }
}

// ================= proj GEMM: [4096,256] x [256,1536] -> k|v|q (cp.async 2-stage) =================
#define PROJ_AS (128 * SMS)
#define PROJ_STB (PROJ_AS * 2)          // stage stride in bytes
#define PROJ_SMEM (8 * PROJ_AS * 2)
__global__ void __launch_bounds__(256) proj_mma_kernel(
    const float* __restrict__ bk, const float* __restrict__ bv, const float* __restrict__ bq)
{
    extern __shared__ __nv_bfloat16 smp[];
    __nv_bfloat16* sAh = smp;
    __nv_bfloat16* sAl = smp + 2 * PROJ_AS;
    __nv_bfloat16* sBh = smp + 4 * PROJ_AS;
    __nv_bfloat16* sBl = smp + 6 * PROJ_AS;

    int t = threadIdx.x, wid = t >> 5, lane = t & 31;
    int warp_m = wid & 1, warp_n = wid >> 1;
    int m0 = blockIdx.y * 128;
    int gn0 = blockIdx.x * 128;
    int sec = gn0 >> 9, wc = gn0 & 511;

    float acc[4][4][4];
#pragma unroll
    for (int i = 0; i < 4; i++)
#pragma unroll
        for (int j = 0; j < 4; j++)
#pragma unroll
            for (int e = 0; e < 4; e++) acc[i][j][e] = 0.f;

    uint32_t uAh = smem_u32(sAh), uAl = smem_u32(sAl);
    uint32_t uBh = smem_u32(sBh), uBl = smem_u32(sBl);

    int ldrow = t >> 2, ldq = t & 3;
    uint32_t so0 = (uint32_t)((ldrow * SMS + ldq * 8) * 2);
    uint32_t so1 = (uint32_t)(((ldrow + 64) * SMS + ldq * 8) * 2);
    const __nv_bfloat16* pA0h = g_lhi  + (size_t)(m0 + ldrow) * DIM + ldq * 8;
    const __nv_bfloat16* pA1h = g_lhi  + (size_t)(m0 + ldrow + 64) * DIM + ldq * 8;
    const __nv_bfloat16* pA0l = g_llo  + (size_t)(m0 + ldrow) * DIM + ldq * 8;
    const __nv_bfloat16* pA1l = g_llo  + (size_t)(m0 + ldrow + 64) * DIM + ldq * 8;
    const __nv_bfloat16* pB0h = g_wthi + (size_t)(gn0 + ldrow) * DIM + ldq * 8;
    const __nv_bfloat16* pB1h = g_wthi + (size_t)(gn0 + ldrow + 64) * DIM + ldq * 8;
    const __nv_bfloat16* pB0l = g_wtlo + (size_t)(gn0 + ldrow) * DIM + ldq * 8;
    const __nv_bfloat16* pB1l = g_wtlo + (size_t)(gn0 + ldrow + 64) * DIM + ldq * 8;

    int arow_a = warp_m * 64 + (lane & 15);
    int aksel  = (lane >> 4) * 8;
    int brow_b = warp_n * 32 + (lane & 7);
    int bksel  = ((lane >> 3) & 1) * 8;

#define PROJ_CP(st_, k0_) do { \
    uint32_t sb_ = (uint32_t)(st_) * PROJ_STB; \
    cp_async16(uAh + sb_ + so0, pA0h + (k0_)); \
    cp_async16(uAh + sb_ + so1, pA1h + (k0_)); \
    cp_async16(uAl + sb_ + so0, pA0l + (k0_)); \
    cp_async16(uAl + sb_ + so1, pA1l + (k0_)); \
    cp_async16(uBh + sb_ + so0, pB0h + (k0_)); \
    cp_async16(uBh + sb_ + so1, pB1h + (k0_)); \
    cp_async16(uBl + sb_ + so0, pB0l + (k0_)); \
    cp_async16(uBl + sb_ + so1, pB1l + (k0_)); \
    CP_COMMIT(); } while (0)

    PROJ_CP(0, 0);

    const int NCH = DIM / 32;  // 8
    for (int ch = 0; ch < NCH; ch++) {
        int cur = ch & 1;
        if (ch + 1 < NCH) { PROJ_CP(cur ^ 1, (ch + 1) * 32); CP_WAIT1(); }
        else              { CP_WAIT0(); }
        __syncthreads();
        uint32_t so = (uint32_t)(cur * PROJ_STB);
#pragma unroll
        for (int ko = 0; ko < 2; ko++) {
            uint32_t ah[4][4], al[4][4], bh[4][2], bl[4][2];
#pragma unroll
            for (int mt = 0; mt < 4; mt++) {
                uint32_t off = so + (uint32_t)(((arow_a + mt * 16) * SMS + ko * 16 + aksel) * 2);
                ldsm_x4(ah[mt], uAh + off);
                ldsm_x4(al[mt], uAl + off);
            }
#pragma unroll
            for (int nt = 0; nt < 4; nt++) {
                uint32_t off = so + (uint32_t)(((brow_b + nt * 8) * SMS + ko * 16 + bksel) * 2);
                ldsm_x2(bh[nt], uBh + off);
                ldsm_x2(bl[nt], uBl + off);
            }
#pragma unroll
            for (int mt = 0; mt < 4; mt++)
#pragma unroll
                for (int nt = 0; nt < 4; nt++) {
                    mma_bf16(acc[mt][nt], ah[mt], bh[nt]);
                    mma_bf16(acc[mt][nt], ah[mt], bl[nt]);
                    mma_bf16(acc[mt][nt], al[mt], bh[nt]);
                }
        }
        __syncthreads();
    }

    const float* bias = (sec == 0) ? bk : ((sec == 1) ? bv : bq);
    float* C = (sec == 0) ? g_k : ((sec == 1) ? g_v : g_q);
    int act = (sec != 1);
    int gid = lane >> 2, tig = lane & 3;

#pragma unroll
    for (int mt = 0; mt < 4; mt++) {
        int row = m0 + warp_m * 64 + mt * 16 + gid;
#pragma unroll
        for (int nt = 0; nt < 4; nt++) {
            int colg = wc + warp_n * 32 + nt * 8 + tig * 2;
            float b0 = bias[colg], b1 = bias[colg + 1];
            float v0 = acc[mt][nt][0] + b0, v1 = acc[mt][nt][1] + b1;
            float v2 = acc[mt][nt][2] + b0, v3 = acc[mt][nt][3] + b1;
            if (act) { v0 = gelu_tanh(v0); v1 = gelu_tanh(v1); v2 = gelu_tanh(v2); v3 = gelu_tanh(v3); }
            *(float2*)(C + (size_t)row * DFF + colg)       = make_float2(v0, v1);
            *(float2*)(C + (size_t)(row + 8) * DFF + colg) = make_float2(v2, v3);
        }
    }
}

// ================= out GEMM: [4096,1024] x [1024,256] -> out (cp.async 2-stage) =================
#define OUT_AS (64 * SMS)
#define OUT_BS (128 * SMS)
#define OUT_ASTB (OUT_AS * 2)
#define OUT_BSTB (OUT_BS * 2)
#define OUT_SMEM ((4 * OUT_AS + 4 * OUT_BS) * 2)
__global__ void __launch_bounds__(256) out_mma_kernel(float* __restrict__ outp)
{
    extern __shared__ __nv_bfloat16 smp[];
    __nv_bfloat16* sAh = smp;
    __nv_bfloat16* sAl = smp + 2 * OUT_AS;
    __nv_bfloat16* sBh = smp + 4 * OUT_AS;
    __nv_bfloat16* sBl = smp + 4 * OUT_AS + 2 * OUT_BS;

    int t = threadIdx.x, wid = t >> 5, lane = t & 31;
    int warp_m = wid & 1, warp_n = wid >> 1;
    int m0 = blockIdx.y * 64;
    int n0 = blockIdx.x * 128;

    float acc[2][4][4];
#pragma unroll
    for (int i = 0; i < 2; i++)
#pragma unroll
        for (int j = 0; j < 4; j++)
#pragma unroll
            for (int e = 0; e < 4; e++) acc[i][j][e] = 0.f;

    uint32_t uAh = smem_u32(sAh), uAl = smem_u32(sAl);
    uint32_t uBh = smem_u32(sBh), uBl = smem_u32(sBl);

    int ldrow = t >> 2, ldq = t & 3;
    uint32_t so0 = (uint32_t)((ldrow * SMS + ldq * 8) * 2);
    uint32_t so1 = (uint32_t)(((ldrow + 64) * SMS + ldq * 8) * 2);
    const __nv_bfloat16* pAh = g_yhi  + (size_t)(m0 + ldrow) * YW + ldq * 8;
    const __nv_bfloat16* pAl = g_ylo  + (size_t)(m0 + ldrow) * YW + ldq * 8;
    const __nv_bfloat16* pB0h = g_wohi + (size_t)(n0 + ldrow) * YW + ldq * 8;
    const __nv_bfloat16* pB1h = g_wohi + (size_t)(n0 + ldrow + 64) * YW + ldq * 8;
    const __nv_bfloat16* pB0l = g_wolo + (size_t)(n0 + ldrow) * YW + ldq * 8;
    const __nv_bfloat16* pB1l = g_wolo + (size_t)(n0 + ldrow + 64) * YW + ldq * 8;

    int arow_a = warp_m * 32 + (lane & 15);
    int aksel  = (lane >> 4) * 8;
    int brow_b = warp_n * 32 + (lane & 7);
    int bksel  = ((lane >> 3) & 1) * 8;

#define OUT_CP(st_, k0_) do { \
    uint32_t sa_ = (uint32_t)(st_) * OUT_ASTB; \
    uint32_t sb_ = (uint32_t)(st_) * OUT_BSTB; \
    cp_async16(uAh + sa_ + so0, pAh + (k0_)); \
    cp_async16(uAl + sa_ + so0, pAl + (k0_)); \
    cp_async16(uBh + sb_ + so0, pB0h + (k0_)); \
    cp_async16(uBh + sb_ + so1, pB1h + (k0_)); \
    cp_async16(uBl + sb_ + so0, pB0l + (k0_)); \
    cp_async16(uBl + sb_ + so1, pB1l + (k0_)); \
    CP_COMMIT(); } while (0)

    OUT_CP(0, 0);

    const int NCH = YW / 32;  // 32
    for (int ch = 0; ch < NCH; ch++) {
        int cur = ch & 1;
        if (ch + 1 < NCH) { OUT_CP(cur ^ 1, (ch + 1) * 32); CP_WAIT1(); }
        else              { CP_WAIT0(); }
        __syncthreads();
        uint32_t soA = (uint32_t)(cur * OUT_ASTB);
        uint32_t soB = (uint32_t)(cur * OUT_BSTB);
#pragma unroll
        for (int ko = 0; ko < 2; ko++) {
            uint32_t ah[2][4], al[2][4], bh[4][2], bl[4][2];
#pragma unroll
            for (int mt = 0; mt < 2; mt++) {
                uint32_t off = soA + (uint32_t)(((arow_a + mt * 16) * SMS + ko * 16 + aksel) * 2);
                ldsm_x4(ah[mt], uAh + off);
                ldsm_x4(al[mt], uAl + off);
            }
#pragma unroll
            for (int nt = 0; nt < 4; nt++) {
                uint32_t off = soB + (uint32_t)(((brow_b + nt * 8) * SMS + ko * 16 + bksel) * 2);
                ldsm_x2(bh[nt], uBh + off);
                ldsm_x2(bl[nt], uBl + off);
            }
#pragma unroll
            for (int mt = 0; mt < 2; mt++)
#pragma unroll
                for (int nt = 0; nt < 4; nt++) {
                    mma_bf16(acc[mt][nt], ah[mt], bh[nt]);
                    mma_bf16(acc[mt][nt], ah[mt], bl[nt]);
                    mma_bf16(acc[mt][nt], al[mt], bh[nt]);
                }
        }
        __syncthreads();
    }

    int gid = lane >> 2, tig = lane & 3;
#pragma unroll
    for (int mt = 0; mt < 2; mt++) {
        int row = m0 + warp_m * 32 + mt * 16 + gid;
#pragma unroll
        for (int nt = 0; nt < 4; nt++) {
            int col = n0 + warp_n * 32 + nt * 8 + tig * 2;
            *(float2*)(outp + (size_t)row * DIM + col) =
                make_float2(acc[mt][nt][0], acc[mt][nt][1]);
            *(float2*)(outp + (size_t)(row + 8) * DIM + col) =
                make_float2(acc[mt][nt][2], acc[mt][nt][3]);
        }
    }
}

// ================= combined seg kernel: chain + batch, fused bmean+split epilogue =================
__global__ void seg_all_kernel(const float* __restrict__ kmat,
                               const float* __restrict__ vmat,
                               const float* __restrict__ qmat,
                               const int* __restrict__ batchv)
{
    int bid = blockIdx.x;
    const int* L;
    int n, col_off, h;
    float inv;
    if (bid < NBATCH * NHEAD) {
        int c = bid >> 3; h = bid & 7;
        L = g_list_batch + c * BA_STRIDE;
        n = g_cnt_batch[c]; inv = g_minv_batch[c];
        col_off = DHEAD;
    } else {
        int idx = bid - NBATCH * NHEAD;
        int c = idx >> 3; h = idx & 7;
        L = g_list_chain + c * CH_STRIDE;
        n = g_cnt_chain[c]; inv = g_minv_chain[c];
        col_off = 0;
    }
    int t = threadIdx.x;

    __shared__ __align__(16) float sm1[64 * 68];
    __shared__ __align__(16) float sm2[64 * 68];

    int ty = t >> 4, tx = t & 15;
    int mloc = t >> 2;
    int part = t & 3;

    float acc[4][4];
#pragma unroll
    for (int i = 0; i < 4; i++)
#pragma unroll
        for (int j = 0; j < 4; j++) acc[i][j] = 0.f;

    int nchunks = (n + 63) >> 6;

    for (int ch = 0; ch < nchunks; ch++) {
        int mrow = ch * 64 + mloc;
        float4 kq[4], vq[4];
        if (mrow < n) {
            int e = L[mrow];
            int i = e & 0x7fffffff;
            float mkf = (e < 0) ? 1.f : 0.f;
            const float4* kp = (const float4*)(kmat + (size_t)i * DFF + h * DHEAD + part * 16);
            const float4* vp = (const float4*)(vmat + (size_t)i * DFF + h * DHEAD + part * 16);
#pragma unroll
            for (int j = 0; j < 4; j++) {
                float4 kk = kp[j];
                kq[j] = make_float4(kk.x * mkf, kk.y * mkf, kk.z * mkf, kk.w * mkf);
                vq[j] = vp[j];
            }
        } else {
#pragma unroll
            for (int j = 0; j < 4; j++) {
                kq[j] = make_float4(0.f, 0.f, 0.f, 0.f);
                vq[j] = make_float4(0.f, 0.f, 0.f, 0.f);
            }
        }
#pragma unroll
        for (int j = 0; j < 4; j++) {
            *(float4*)(sm1 + mloc * 68 + part * 16 + j * 4) = kq[j];
            *(float4*)(sm2 + mloc * 68 + part * 16 + j * 4) = vq[j];
        }
        __syncthreads();

#pragma unroll 4
        for (int m = 0; m < 64; m++) {
            float4 af = *(const float4*)(sm1 + m * 68 + ty * 4);
            float4 bf = *(const float4*)(sm2 + m * 68 + tx * 4);
            acc[0][0] += af.x * bf.x; acc[0][1] += af.x * bf.y;
            acc[0][2] += af.x * bf.z; acc[0][3] += af.x * bf.w;
            acc[1][0] += af.y * bf.x; acc[1][1] += af.y * bf.y;
            acc[1][2] += af.y * bf.z; acc[1][3] += af.y * bf.w;
            acc[2][0] += af.z * bf.x; acc[2][1] += af.z * bf.y;
            acc[2][2] += af.z * bf.z; acc[2][3] += af.z * bf.w;
            acc[3][0] += af.w * bf.x; acc[3][1] += af.w * bf.y;
            acc[3][2] += af.w * bf.z; acc[3][3] += af.w * bf.w;
        }
        __syncthreads();
    }

#pragma unroll
    for (int i = 0; i < 4; i++)
#pragma unroll
        for (int j = 0; j < 4; j++)
            sm1[(ty * 4 + i) * 68 + tx * 4 + j] = acc[i][j] * inv;
    __syncthreads();

    int colbase = h * 128 + col_off + tx * 4;

    for (int ch = 0; ch < nchunks; ch++) {
        int mrow = ch * 64 + mloc;
        float4 qq[4];
        if (mrow < n) {
            int i = L[mrow] & 0x7fffffff;
            const float4* qp = (const float4*)(qmat + (size_t)i * DFF + h * DHEAD + part * 16);
#pragma unroll
            for (int j = 0; j < 4; j++) qq[j] = qp[j];
        } else {
#pragma unroll
            for (int j = 0; j < 4; j++) qq[j] = make_float4(0.f, 0.f, 0.f, 0.f);
        }
#pragma unroll
        for (int j = 0; j < 4; j++)
            *(float4*)(sm2 + mloc * 68 + part * 16 + j * 4) = qq[j];
        __syncthreads();

        float o[4][4];
#pragma unroll
        for (int i = 0; i < 4; i++)
#pragma unroll
            for (int j = 0; j < 4; j++) o[i][j] = 0.f;

#pragma unroll 8
        for (int b = 0; b < 64; b += 4) {
#pragma unroll
            for (int i = 0; i < 4; i++) {
                float4 qf = *(const float4*)(sm2 + (ty * 4 + i) * 68 + b);
#pragma unroll
                for (int j = 0; j < 4; j++) {
                    float4 af = *(const float4*)(sm1 + (tx * 4 + j) * 68 + b);
                    o[i][j] += qf.x * af.x + qf.y * af.y + qf.z * af.z + qf.w * af.w;
                }
            }
        }

#pragma unroll
        for (int i = 0; i < 4; i++) {
            int mm = ch * 64 + ty * 4 + i;
            if (mm < n) {
                int irow = L[mm] & 0x7fffffff;
                int bb = batchv[irow];
                float4 bm = *(const float4*)(g_bmean + (size_t)bb * YW + colbase);
                __nv_bfloat16 h0, l0, h1, l1, h2, l2, h3, l3;
                split2(o[i][0] + bm.x, h0, l0);
                split2(o[i][1] + bm.y, h1, l1);
                split2(o[i][2] + bm.z, h2, l2);
                split2(o[i][3] + bm.w, h3, l3);
                __nv_bfloat16* ph = g_yhi + (size_t)irow * YW + colbase;
                __nv_bfloat16* pl = g_ylo + (size_t)irow * YW + colbase;
                *(__nv_bfloat162*)(ph)     = __nv_bfloat162(h0, h1);
                *(__nv_bfloat162*)(ph + 2) = __nv_bfloat162(h2, h3);
                *(__nv_bfloat162*)(pl)     = __nv_bfloat162(l0, l1);
                *(__nv_bfloat162*)(pl + 2) = __nv_bfloat162(l2, l3);
            }
        }
        __syncthreads();
    }
}

// ================= launch =================
extern "C" void kernel_launch(void* const* d_in, const int* in_sizes, int n_in,
                              void* d_out, int out_size)
{
    const float* local   = (const float*)d_in[0];
    const int*   chain   = (const int*)  d_in[1];
    const int*   batch   = (const int*)  d_in[2];
    const void*  mask    = d_in[3];
    const float* W_key   = (const float*)d_in[4];
    const float* b_key   = (const float*)d_in[5];
    const float* W_value = (const float*)d_in[6];
    const float* b_value = (const float*)d_in[7];
    const float* W_query = (const float*)d_in[8];
    const float* b_query = (const float*)d_in[9];
    const float* W_bias  = (const float*)d_in[10];
    const float* b_bias  = (const float*)d_in[11];
    const float* W_out   = (const float*)d_in[12];
    float* out = (float*)d_out;

    float *gk, *gv, *gq;
    cudaGetSymbolAddress((void**)&gk, g_k);
    cudaGetSymbolAddress((void**)&gv, g_v);
    cudaGetSymbolAddress((void**)&gq, g_q);

    static bool attr_done = false;
    if (!attr_done) {
        cudaFuncSetAttribute(proj_mma_kernel, cudaFuncAttributeMaxDynamicSharedMemorySize, PROJ_SMEM);
        cudaFuncSetAttribute(out_mma_kernel,  cudaFuncAttributeMaxDynamicSharedMemorySize, OUT_SMEM);
        attr_done = true;
    }

    mask_kernel<<<1, 1024>>>((const unsigned char*)mask);

    build_all_kernel<<<NBATCH + NCHAIN, 1024>>>(chain, batch, local, W_bias, b_bias);

    split_local_kernel<<<NROWS * DIM / 1024, 256>>>(local);
    wtsplit_kernel<<<dim3(16, 32, 4), dim3(32, 8)>>>(W_key, W_value, W_query, W_out);

    proj_mma_kernel<<<dim3(1536 / 128, NROWS / 128), 256, PROJ_SMEM>>>(b_key, b_value, b_query);

    seg_all_kernel<<<NBATCH * NHEAD + NCHAIN * NHEAD, 256>>>(gk, gv, gq, batch);

    out_mma_kernel<<<dim3(DIM / 128, NROWS / 64), 256, OUT_SMEM>>>(out);
}